// round 9
// baseline (speedup 1.0000x reference)
#include <cuda_runtime.h>

#define NN 100000
#define NE 1600000
#define ET (NE + NN)

typedef unsigned long long u64;

// -------- scratch (device globals: no allocations allowed) --------
__device__ int   g_col[ET];       // CSR column (src) indices, sorted by dst
__device__ int   g_deg[NN];       // reset inside scan_scatter after scan consumes it
__device__ int   g_rp[NN + 1];    // CSR row pointers
__device__ int   g_cur[NN];       // scatter cursors
__device__ int   g_flag;          // scan-done flag (cleared by hist)
__device__ float g_h1[NN * 128];  // layer1 features [N,8,16]
__device__ float g_as1[NN * 8];
__device__ float g_ad1[NN * 8];
__device__ float g_o1[NN * 128];  // layer1 out (bias+elu applied) = h2
__device__ float g_z[NN * 40];    // layer2 features
__device__ float g_as2[NN];
__device__ float g_ad2[NN];

__device__ __forceinline__ float lrelu(float v) { return v > 0.f ? v : 0.2f * v; }

__device__ __forceinline__ void ffma2(u64& d, u64 a, u64 b) {
    asm("fma.rn.f32x2 %0, %1, %2, %0;" : "+l"(d) : "l"(a), "l"(b));
}
__device__ __forceinline__ void upk2(float& lo, float& hi, u64 v) {
    asm("mov.b64 {%0, %1}, %2;" : "=f"(lo), "=f"(hi) : "l"(v));
}

__device__ __forceinline__ int detect64(const int* e32) {
    int z = 0;
#pragma unroll
    for (int j = 1; j <= 16; j++) z |= e32[2 * j + 1];
    return (z == 0) ? 1 : 0;
}

// ==================== CSR build ====================
__global__ void hist_kernel(const int* __restrict__ e32) {
    __shared__ int is64;
    if (threadIdx.x == 0) is64 = detect64(e32);
    __syncthreads();
    int i = blockIdx.x * blockDim.x + threadIdx.x;
    if (i == 0) g_flag = 0;   // reset scan-done flag for this replay
    if (i >= ET) return;
    int d;
    if (i < NE) d = is64 ? e32[2 * (NE + i)] : e32[NE + i];
    else        d = i - NE;
    atomicAdd(&g_deg[d], 1);
}

// Fused scan + scatter. Block 0 (1024 thr) computes the exclusive scan of
// g_deg into g_rp/g_cur, fences, sets g_flag. All blocks then scatter.
__global__ void scan_scatter(const int* __restrict__ e32) {
    __shared__ int is64s;
    int tid = threadIdx.x;

    if (blockIdx.x == 0) {
        __shared__ int wsum[32];
        __shared__ int stot;
        int lane = tid & 31, wid = tid >> 5;
        int run = 0;
        int v = (tid < NN) ? g_deg[tid] : 0;
        for (int base = 0; base < NN; base += 1024) {
            int inx = base + 1024 + tid;
            int vn = (inx < NN) ? g_deg[inx] : 0;   // prefetch next tile
            int x = v;
#pragma unroll
            for (int off = 1; off < 32; off <<= 1) {
                int y = __shfl_up_sync(0xffffffffu, x, off);
                if (lane >= off) x += y;
            }
            if (lane == 31) wsum[wid] = x;
            __syncthreads();
            if (wid == 0) {
                int wv = wsum[lane];
#pragma unroll
                for (int off = 1; off < 32; off <<= 1) {
                    int y = __shfl_up_sync(0xffffffffu, wv, off);
                    if (lane >= off) wv += y;
                }
                wsum[lane] = wv;
                if (lane == 31) stot = wv;
            }
            __syncthreads();
            int incl = x + (wid > 0 ? wsum[wid - 1] : 0) + run;
            int ii = base + tid;
            if (ii < NN) {
                g_rp[ii + 1] = incl;
                g_cur[ii] = incl - v;
            }
            run += stot;
            __syncthreads();
            v = vn;
        }
        if (tid == 0) {
            g_rp[0] = 0;
            __threadfence();
            atomicExch(&g_flag, 1);
        }
        __syncthreads();
    } else {
        if (tid == 0) {
            while (atomicAdd(&g_flag, 0) == 0) __nanosleep(128);
        }
        __syncthreads();
    }

    if (tid == 0) is64s = detect64(e32);
    __syncthreads();
    int is64 = is64s;

    int i = blockIdx.x * 1024 + tid;
    if (i < NN) g_deg[i] = 0;   // reset for next replay (scan already consumed)
    if (i >= ET) return;
    int s, d;
    if (i < NE) {
        if (is64) { s = e32[2 * i]; d = e32[2 * (NE + i)]; }
        else      { s = e32[i];     d = e32[NE + i]; }
    } else {
        s = d = i - NE;
    }
    int pos = atomicAdd(&g_cur[d], 1);
    g_col[pos] = s;
}

// ==================== GEMM1: h1 = x @ W1 (LDS.128 f32x2), + attention dots ====================
__global__ void gemm1_kernel(const float* __restrict__ x, const float* __restrict__ W,
                             const float* __restrict__ atts, const float* __restrict__ attd) {
    extern __shared__ float sm[];
    float* xs = sm + 16384;    // 64*132 floats
    int t = threadIdx.x;
    int ct = t & 31, rt = t >> 5;
    int row0 = blockIdx.x * 64;

    for (int i = t; i < 4096; i += 256) {     // pack W: [kpp][e][q][4k]
        int k = i >> 5, q = i & 31;
        float4 v = *(const float4*)&W[k * 128 + q * 4];
        float* dst = sm + (k >> 2) * 512 + q * 4 + (k & 3);
        dst[0] = v.x; dst[128] = v.y; dst[256] = v.z; dst[384] = v.w;
    }
    for (int i = t; i < 2048; i += 256) {
        int r = i >> 5, k4 = (i & 31) * 4;
        int row = row0 + r;
        float4 v = (row < NN) ? *(const float4*)&x[row * 128 + k4]
                              : make_float4(0.f, 0.f, 0.f, 0.f);
        *(float4*)&xs[r * 132 + k4] = v;
    }
    __syncthreads();

    u64 acc2[8][4];
#pragma unroll
    for (int i = 0; i < 8; i++)
#pragma unroll
        for (int c = 0; c < 4; c++) acc2[i][c] = 0ull;

#pragma unroll 2
    for (int kpp = 0; kpp < 32; kpp++) {      // 4 k per iteration
        const float* wb = sm + kpp * 512 + 4 * ct;
        ulonglong2 w0 = *(const ulonglong2*)(wb);
        ulonglong2 w1 = *(const ulonglong2*)(wb + 128);
        ulonglong2 w2 = *(const ulonglong2*)(wb + 256);
        ulonglong2 w3 = *(const ulonglong2*)(wb + 384);
#pragma unroll
        for (int i = 0; i < 8; i++) {
            ulonglong2 xp = *(const ulonglong2*)&xs[(rt * 8 + i) * 132 + 4 * kpp];
            ffma2(acc2[i][0], xp.x, w0.x); ffma2(acc2[i][0], xp.y, w0.y);
            ffma2(acc2[i][1], xp.x, w1.x); ffma2(acc2[i][1], xp.y, w1.y);
            ffma2(acc2[i][2], xp.x, w2.x); ffma2(acc2[i][2], xp.y, w2.y);
            ffma2(acc2[i][3], xp.x, w3.x); ffma2(acc2[i][3], xp.y, w3.y);
        }
    }

    float4 avs = *(const float4*)&atts[4 * ct];
    float4 avd = *(const float4*)&attd[4 * ct];
#pragma unroll
    for (int i = 0; i < 8; i++) {
        float a[4];
#pragma unroll
        for (int c = 0; c < 4; c++) {
            float lo, hi; upk2(lo, hi, acc2[i][c]);
            a[c] = lo + hi;
        }
        int row = row0 + rt * 8 + i;
        if (row < NN) {
            *(float4*)&g_h1[row * 128 + 4 * ct] = make_float4(a[0], a[1], a[2], a[3]);
            float ps = a[0] * avs.x + a[1] * avs.y + a[2] * avs.z + a[3] * avs.w;
            float pd = a[0] * avd.x + a[1] * avd.y + a[2] * avd.z + a[3] * avd.w;
            ps += __shfl_xor_sync(0xffffffffu, ps, 1);
            ps += __shfl_xor_sync(0xffffffffu, ps, 2);
            pd += __shfl_xor_sync(0xffffffffu, pd, 1);
            pd += __shfl_xor_sync(0xffffffffu, pd, 2);
            if ((ct & 3) == 0) {
                g_as1[row * 8 + (ct >> 2)] = ps;
                g_ad1[row * 8 + (ct >> 2)] = pd;
            }
        }
    }
}

// ==================== fused layer1: single-pass unnormalized aggregate (R7 form) ====================
__global__ void l1_gather(const float* __restrict__ b1) {
    __shared__ float sex[8][8][32];   // [warp][head][edge-in-chunk]
    int w = (blockIdx.x * blockDim.x + threadIdx.x) >> 5;
    int wid = (threadIdx.x >> 5) & 7;
    int lane = threadIdx.x & 31;
    if (w >= NN) return;
    int beg = g_rp[w], end = g_rp[w + 1];

    float4 ad0 = *(const float4*)&g_ad1[w * 8];
    float4 ad1v = *(const float4*)&g_ad1[w * 8 + 4];

    int h = lane >> 2;
    float dn[8] = {};
    float4 acc = make_float4(0.f, 0.f, 0.f, 0.f);

    for (int base = beg; base < end; base += 32) {
        int idx = base + lane;
        int sc = (idx < end) ? g_col[idx] : 0;
        float msk = (idx < end) ? 1.f : 0.f;
        {
            float4 s0 = *(const float4*)&g_as1[sc * 8];
            float4 s1 = *(const float4*)&g_as1[sc * 8 + 4];
            float e0 = __expf(lrelu(s0.x + ad0.x)) * msk;
            float e1 = __expf(lrelu(s0.y + ad0.y)) * msk;
            float e2 = __expf(lrelu(s0.z + ad0.z)) * msk;
            float e3 = __expf(lrelu(s0.w + ad0.w)) * msk;
            float e4 = __expf(lrelu(s1.x + ad1v.x)) * msk;
            float e5 = __expf(lrelu(s1.y + ad1v.y)) * msk;
            float e6 = __expf(lrelu(s1.z + ad1v.z)) * msk;
            float e7 = __expf(lrelu(s1.w + ad1v.w)) * msk;
            sex[wid][0][lane] = e0; dn[0] += e0;
            sex[wid][1][lane] = e1; dn[1] += e1;
            sex[wid][2][lane] = e2; dn[2] += e2;
            sex[wid][3][lane] = e3; dn[3] += e3;
            sex[wid][4][lane] = e4; dn[4] += e4;
            sex[wid][5][lane] = e5; dn[5] += e5;
            sex[wid][6][lane] = e6; dn[6] += e6;
            sex[wid][7][lane] = e7; dn[7] += e7;
        }
        __syncwarp();
        int n = min(32, end - base);
#pragma unroll 4
        for (int j = 0; j < n; j++) {
            int s = __shfl_sync(0xffffffffu, sc, j);
            float a = sex[wid][h][j];
            float4 v = *(const float4*)&g_h1[s * 128 + lane * 4];
            acc.x += a * v.x; acc.y += a * v.y;
            acc.z += a * v.z; acc.w += a * v.w;
        }
        __syncwarp();
    }

#pragma unroll
    for (int hh = 0; hh < 8; hh++)
        for (int off = 16; off; off >>= 1)
            dn[hh] += __shfl_xor_sync(0xffffffffu, dn[hh], off);
    float rdn = 1.f / (dn[h] + 1e-16f);

    float4 bb = *(const float4*)&b1[lane * 4];
    acc.x = acc.x * rdn + bb.x;
    acc.y = acc.y * rdn + bb.y;
    acc.z = acc.z * rdn + bb.z;
    acc.w = acc.w * rdn + bb.w;
    acc.x = acc.x > 0.f ? acc.x : expm1f(acc.x);
    acc.y = acc.y > 0.f ? acc.y : expm1f(acc.y);
    acc.z = acc.z > 0.f ? acc.z : expm1f(acc.z);
    acc.w = acc.w > 0.f ? acc.w : expm1f(acc.w);
    *(float4*)&g_o1[w * 128 + lane * 4] = acc;
}

// ==================== GEMM2 (128->40, LDS.128 f32x2) with fused a2 dots ====================
__global__ void gemm2_kernel(const float* __restrict__ W,
                             const float* __restrict__ atts, const float* __restrict__ attd) {
    extern __shared__ float sm[];
    float* xs = sm + 5120;           // 64*132
    float* sa = sm + 5120 + 8448;    // 64
    float* sd = sa + 64;             // 64
    int t = threadIdx.x;
    int ct = t % 10, rt = t / 10;
    int row0 = blockIdx.x * 64;

    for (int i = t; i < 5120; i += 160) {   // pack W: [kpp][e][q][kk]
        int k = i / 40, c = i % 40;
        sm[(k >> 2) * 160 + (c & 3) * 40 + (c >> 2) * 4 + (k & 3)] = W[i];
    }
    for (int i = t; i < 2048; i += 160) {
        int r = i >> 5, k4 = (i & 31) * 4;
        int row = row0 + r;
        float4 v = (row < NN) ? *(const float4*)&g_o1[row * 128 + k4]
                              : make_float4(0.f, 0.f, 0.f, 0.f);
        *(float4*)&xs[r * 132 + k4] = v;
    }
    if (t < 64) { sa[t] = 0.f; sd[t] = 0.f; }
    __syncthreads();

    u64 acc2[4][4];
#pragma unroll
    for (int i = 0; i < 4; i++)
#pragma unroll
        for (int c = 0; c < 4; c++) acc2[i][c] = 0ull;

#pragma unroll 2
    for (int kpp = 0; kpp < 32; kpp++) {
        const float* wb = sm + kpp * 160 + 4 * ct;
        ulonglong2 w0 = *(const ulonglong2*)(wb);
        ulonglong2 w1 = *(const ulonglong2*)(wb + 40);
        ulonglong2 w2 = *(const ulonglong2*)(wb + 80);
        ulonglong2 w3 = *(const ulonglong2*)(wb + 120);
#pragma unroll
        for (int i = 0; i < 4; i++) {
            ulonglong2 xp = *(const ulonglong2*)&xs[(rt * 4 + i) * 132 + 4 * kpp];
            ffma2(acc2[i][0], xp.x, w0.x); ffma2(acc2[i][0], xp.y, w0.y);
            ffma2(acc2[i][1], xp.x, w1.x); ffma2(acc2[i][1], xp.y, w1.y);
            ffma2(acc2[i][2], xp.x, w2.x); ffma2(acc2[i][2], xp.y, w2.y);
            ffma2(acc2[i][3], xp.x, w3.x); ffma2(acc2[i][3], xp.y, w3.y);
        }
    }

    float4 avs = *(const float4*)&atts[4 * ct];
    float4 avd = *(const float4*)&attd[4 * ct];
#pragma unroll
    for (int i = 0; i < 4; i++) {
        float a[4];
#pragma unroll
        for (int c = 0; c < 4; c++) {
            float lo, hi; upk2(lo, hi, acc2[i][c]);
            a[c] = lo + hi;
        }
        int row = row0 + rt * 4 + i;
        if (row < NN)
            *(float4*)&g_z[row * 40 + 4 * ct] = make_float4(a[0], a[1], a[2], a[3]);
        float ps = a[0] * avs.x + a[1] * avs.y + a[2] * avs.z + a[3] * avs.w;
        float pd = a[0] * avd.x + a[1] * avd.y + a[2] * avd.z + a[3] * avd.w;
        atomicAdd(&sa[rt * 4 + i], ps);
        atomicAdd(&sd[rt * 4 + i], pd);
    }
    __syncthreads();
    if (t < 64) {
        int row = row0 + t;
        if (row < NN) { g_as2[row] = sa[t]; g_ad2[row] = sd[t]; }
    }
}

// ==================== fused layer2: single-pass + bias + log_softmax (R7 form) ====================
__global__ void l2_gather(float* __restrict__ out, const float* __restrict__ b2) {
    int w = (blockIdx.x * blockDim.x + threadIdx.x) >> 5;
    int lane = threadIdx.x & 31;
    if (w >= NN) return;
    int beg = g_rp[w], end = g_rp[w + 1];
    float adw = g_ad2[w];

    float dn = 0.f;
    float a1 = 0.f, a2 = 0.f;
    for (int base = beg; base < end; base += 32) {
        int idx = base + lane;
        int sc = (idx < end) ? g_col[idx] : 0;
        float ex = (idx < end) ? __expf(lrelu(g_as2[sc] + adw)) : 0.f;
        dn += ex;
        int n = min(32, end - base);
#pragma unroll 4
        for (int j = 0; j < n; j++) {
            float al = __shfl_sync(0xffffffffu, ex, j);
            int s = __shfl_sync(0xffffffffu, sc, j);
            a1 += al * g_z[s * 40 + lane];
            if (lane < 8) a2 += al * g_z[s * 40 + 32 + lane];
        }
    }
    for (int off = 16; off; off >>= 1)
        dn += __shfl_xor_sync(0xffffffffu, dn, off);
    float rdn = 1.f / (dn + 1e-16f);

    float v1 = a1 * rdn + b2[lane];
    float v2 = (lane < 8) ? a2 * rdn + b2[32 + lane] : -1e30f;
    float m = fmaxf(v1, v2);
    for (int o = 16; o; o >>= 1) m = fmaxf(m, __shfl_xor_sync(0xffffffffu, m, o));
    float s = expf(v1 - m) + ((lane < 8) ? expf(v2 - m) : 0.f);
    for (int o = 16; o; o >>= 1) s += __shfl_xor_sync(0xffffffffu, s, o);
    float ls = m + logf(s);
    out[w * 40 + lane] = v1 - ls;
    if (lane < 8) out[w * 40 + 32 + lane] = v2 - ls;
}

// ==================== launch ====================
extern "C" void kernel_launch(void* const* d_in, const int* in_sizes, int n_in,
                              void* d_out, int out_size) {
    const float* x   = (const float*)d_in[0];
    const int*   ei  = (const int*)d_in[1];
    const float* W1  = (const float*)d_in[2];
    const float* as1 = (const float*)d_in[3];
    const float* ad1 = (const float*)d_in[4];
    const float* b1  = (const float*)d_in[5];
    const float* W2  = (const float*)d_in[6];
    const float* as2 = (const float*)d_in[7];
    const float* ad2 = (const float*)d_in[8];
    const float* b2  = (const float*)d_in[9];
    float* out = (float*)d_out;

    static cudaStream_t sB = nullptr;
    static cudaEvent_t evF = nullptr, evJ = nullptr;
    if (!sB) {
        cudaStreamCreateWithFlags(&sB, cudaStreamNonBlocking);
        cudaEventCreateWithFlags(&evF, cudaEventDisableTiming);
        cudaEventCreateWithFlags(&evJ, cudaEventDisableTiming);
    }

    const int SM1 = (16384 + 64 * 132) * 4;          // 99328 B
    const int SM2 = (5120 + 64 * 132 + 128) * 4;     // 54784 B
    cudaFuncSetAttribute(gemm1_kernel, cudaFuncAttributeMaxDynamicSharedMemorySize, SM1);
    cudaFuncSetAttribute(gemm2_kernel, cudaFuncAttributeMaxDynamicSharedMemorySize, SM2);

    // fork: CSR build on side stream, gemm1 on main stream.
    // Launch order: hist(0), scan_scatter(1), gemm1(2), l1_gather(3) <- profiled slot.
    cudaEventRecord(evF, 0);
    cudaStreamWaitEvent(sB, evF, 0);

    hist_kernel<<<(ET + 255) / 256, 256, 0, sB>>>(ei);       // 0
    scan_scatter<<<(ET + 1023) / 1024, 1024, 0, sB>>>(ei);   // 1
    cudaEventRecord(evJ, sB);

    gemm1_kernel<<<(NN + 63) / 64, 256, SM1>>>(x, W1, as1, ad1);   // 2

    cudaStreamWaitEvent(0, evJ, 0);

    l1_gather<<<(NN * 32 + 255) / 256, 256>>>(b1);           // 3 <- profiled
    gemm2_kernel<<<(NN + 63) / 64, 160, SM2>>>(W2, as2, ad2);// 4
    l2_gather<<<(NN * 32 + 255) / 256, 256>>>(out, b2);      // 5
}

// round 10
// speedup vs baseline: 1.0936x; 1.0936x over previous
#include <cuda_runtime.h>

#define NN 100000
#define NE 1600000
#define ET (NE + NN)
#define NB 98   // ceil(NN/1024) scan blocks

typedef unsigned long long u64;

// -------- scratch (device globals: no allocations allowed) --------
__device__ int   g_col[ET];       // CSR column (src) indices, sorted by dst
__device__ int   g_deg[NN];       // zeroed at end of scatter for next replay
__device__ int   g_scan[NN];
__device__ int   g_bsum[NB];
__device__ int   g_boff[NB];
__device__ int   g_rp[NN + 1];    // CSR row pointers
__device__ int   g_cur[NN];       // scatter cursors
__device__ float g_h1[NN * 128];  // layer1 features [N,8,16]
__device__ float g_as1[NN * 8];
__device__ float g_ad1[NN * 8];
__device__ float g_o1[NN * 128];  // layer1 out (bias+elu applied) = h2
__device__ float g_z[NN * 40];    // layer2 features
__device__ float g_as2[NN];
__device__ float g_ad2[NN];

__device__ __forceinline__ float lrelu(float v) { return v > 0.f ? v : 0.2f * v; }

__device__ __forceinline__ void ffma2(u64& d, u64 a, u64 b) {
    asm("fma.rn.f32x2 %0, %1, %2, %0;" : "+l"(d) : "l"(a), "l"(b));
}
__device__ __forceinline__ void upk2(float& lo, float& hi, u64 v) {
    asm("mov.b64 {%0, %1}, %2;" : "=f"(lo), "=f"(hi) : "l"(v));
}

__device__ __forceinline__ int detect64(const int* e32) {
    int z = 0;
#pragma unroll
    for (int j = 1; j <= 16; j++) z |= e32[2 * j + 1];
    return (z == 0) ? 1 : 0;
}

// ==================== CSR build (R7 structure: no spinning) ====================
__global__ void hist_kernel(const int* __restrict__ e32) {
    __shared__ int is64;
    if (threadIdx.x == 0) is64 = detect64(e32);
    __syncthreads();
    int i = blockIdx.x * blockDim.x + threadIdx.x;
    if (i >= ET) return;
    int d;
    if (i < NE) d = is64 ? e32[2 * (NE + i)] : e32[NE + i];
    else        d = i - NE;
    atomicAdd(&g_deg[d], 1);
}

__global__ void scan1() {
    __shared__ int sm[1024];
    int i = blockIdx.x * 1024 + threadIdx.x;
    int v = (i < NN) ? g_deg[i] : 0;
    sm[threadIdx.x] = v;
    __syncthreads();
    for (int off = 1; off < 1024; off <<= 1) {
        int t = (threadIdx.x >= off) ? sm[threadIdx.x - off] : 0;
        __syncthreads();
        sm[threadIdx.x] += t;
        __syncthreads();
    }
    if (i < NN) g_scan[i] = sm[threadIdx.x];
    if (threadIdx.x == 1023) g_bsum[blockIdx.x] = sm[1023];
}

__global__ void scan2() {
    __shared__ int sm[128];
    int t = threadIdx.x;
    int v = (t < NB) ? g_bsum[t] : 0;
    sm[t] = v;
    __syncthreads();
    for (int off = 1; off < 128; off <<= 1) {
        int a = (t >= off) ? sm[t - off] : 0;
        __syncthreads();
        sm[t] += a;
        __syncthreads();
    }
    if (t < NB) g_boff[t] = sm[t] - v;   // exclusive
}

__global__ void scan3() {
    int i = blockIdx.x * blockDim.x + threadIdx.x;
    if (i >= NN) return;
    int incl = g_scan[i] + g_boff[i >> 10];
    g_rp[i + 1] = incl;
    g_cur[i] = incl - g_deg[i];
    if (i == 0) g_rp[0] = 0;
}

__global__ void scatter(const int* __restrict__ e32) {
    __shared__ int is64;
    if (threadIdx.x == 0) is64 = detect64(e32);
    __syncthreads();
    int i = blockIdx.x * blockDim.x + threadIdx.x;
    if (i < NN) g_deg[i] = 0;   // reset for next replay (deg already consumed)
    if (i >= ET) return;
    int s, d;
    if (i < NE) {
        if (is64) { s = e32[2 * i]; d = e32[2 * (NE + i)]; }
        else      { s = e32[i];     d = e32[NE + i]; }
    } else {
        s = d = i - NE;
    }
    int pos = atomicAdd(&g_cur[d], 1);
    g_col[pos] = s;
}

// ==================== GEMM1: h1 = x @ W1 (LDS.128 f32x2), + attention dots ====================
__global__ void gemm1_kernel(const float* __restrict__ x, const float* __restrict__ W,
                             const float* __restrict__ atts, const float* __restrict__ attd) {
    extern __shared__ float sm[];
    float* xs = sm + 16384;    // 64*132 floats
    int t = threadIdx.x;
    int ct = t & 31, rt = t >> 5;
    int row0 = blockIdx.x * 64;

    for (int i = t; i < 4096; i += 256) {     // pack W: [kpp][e][q][4k]
        int k = i >> 5, q = i & 31;
        float4 v = *(const float4*)&W[k * 128 + q * 4];
        float* dst = sm + (k >> 2) * 512 + q * 4 + (k & 3);
        dst[0] = v.x; dst[128] = v.y; dst[256] = v.z; dst[384] = v.w;
    }
    for (int i = t; i < 2048; i += 256) {
        int r = i >> 5, k4 = (i & 31) * 4;
        int row = row0 + r;
        float4 v = (row < NN) ? *(const float4*)&x[row * 128 + k4]
                              : make_float4(0.f, 0.f, 0.f, 0.f);
        *(float4*)&xs[r * 132 + k4] = v;
    }
    __syncthreads();

    u64 acc2[8][4];
#pragma unroll
    for (int i = 0; i < 8; i++)
#pragma unroll
        for (int c = 0; c < 4; c++) acc2[i][c] = 0ull;

#pragma unroll 2
    for (int kpp = 0; kpp < 32; kpp++) {      // 4 k per iteration
        const float* wb = sm + kpp * 512 + 4 * ct;
        ulonglong2 w0 = *(const ulonglong2*)(wb);
        ulonglong2 w1 = *(const ulonglong2*)(wb + 128);
        ulonglong2 w2 = *(const ulonglong2*)(wb + 256);
        ulonglong2 w3 = *(const ulonglong2*)(wb + 384);
#pragma unroll
        for (int i = 0; i < 8; i++) {
            ulonglong2 xp = *(const ulonglong2*)&xs[(rt * 8 + i) * 132 + 4 * kpp];
            ffma2(acc2[i][0], xp.x, w0.x); ffma2(acc2[i][0], xp.y, w0.y);
            ffma2(acc2[i][1], xp.x, w1.x); ffma2(acc2[i][1], xp.y, w1.y);
            ffma2(acc2[i][2], xp.x, w2.x); ffma2(acc2[i][2], xp.y, w2.y);
            ffma2(acc2[i][3], xp.x, w3.x); ffma2(acc2[i][3], xp.y, w3.y);
        }
    }

    float4 avs = *(const float4*)&atts[4 * ct];
    float4 avd = *(const float4*)&attd[4 * ct];
#pragma unroll
    for (int i = 0; i < 8; i++) {
        float a[4];
#pragma unroll
        for (int c = 0; c < 4; c++) {
            float lo, hi; upk2(lo, hi, acc2[i][c]);
            a[c] = lo + hi;
        }
        int row = row0 + rt * 8 + i;
        if (row < NN) {
            *(float4*)&g_h1[row * 128 + 4 * ct] = make_float4(a[0], a[1], a[2], a[3]);
            float ps = a[0] * avs.x + a[1] * avs.y + a[2] * avs.z + a[3] * avs.w;
            float pd = a[0] * avd.x + a[1] * avd.y + a[2] * avd.z + a[3] * avd.w;
            ps += __shfl_xor_sync(0xffffffffu, ps, 1);
            ps += __shfl_xor_sync(0xffffffffu, ps, 2);
            pd += __shfl_xor_sync(0xffffffffu, pd, 1);
            pd += __shfl_xor_sync(0xffffffffu, pd, 2);
            if ((ct & 3) == 0) {
                g_as1[row * 8 + (ct >> 2)] = ps;
                g_ad1[row * 8 + (ct >> 2)] = pd;
            }
        }
    }
}

// ==================== fused layer1: single-pass, bank-conflict-free staging ====================
__global__ void l1_gather(const float* __restrict__ b1) {
    __shared__ float sex[8][8][33];   // [warp][head][edge]; 33 pad -> banks (h+j)%32 distinct
    int w = (blockIdx.x * blockDim.x + threadIdx.x) >> 5;
    int wid = (threadIdx.x >> 5) & 7;
    int lane = threadIdx.x & 31;
    if (w >= NN) return;
    int beg = g_rp[w], end = g_rp[w + 1];

    float4 ad0 = *(const float4*)&g_ad1[w * 8];
    float4 ad1v = *(const float4*)&g_ad1[w * 8 + 4];

    int h = lane >> 2;
    float dn[8] = {};
    float4 acc = make_float4(0.f, 0.f, 0.f, 0.f);

    for (int base = beg; base < end; base += 32) {
        int idx = base + lane;
        int sc = (idx < end) ? g_col[idx] : 0;
        float msk = (idx < end) ? 1.f : 0.f;
        {
            float4 s0 = *(const float4*)&g_as1[sc * 8];
            float4 s1 = *(const float4*)&g_as1[sc * 8 + 4];
            float e0 = __expf(lrelu(s0.x + ad0.x)) * msk;
            float e1 = __expf(lrelu(s0.y + ad0.y)) * msk;
            float e2 = __expf(lrelu(s0.z + ad0.z)) * msk;
            float e3 = __expf(lrelu(s0.w + ad0.w)) * msk;
            float e4 = __expf(lrelu(s1.x + ad1v.x)) * msk;
            float e5 = __expf(lrelu(s1.y + ad1v.y)) * msk;
            float e6 = __expf(lrelu(s1.z + ad1v.z)) * msk;
            float e7 = __expf(lrelu(s1.w + ad1v.w)) * msk;
            sex[wid][0][lane] = e0; dn[0] += e0;
            sex[wid][1][lane] = e1; dn[1] += e1;
            sex[wid][2][lane] = e2; dn[2] += e2;
            sex[wid][3][lane] = e3; dn[3] += e3;
            sex[wid][4][lane] = e4; dn[4] += e4;
            sex[wid][5][lane] = e5; dn[5] += e5;
            sex[wid][6][lane] = e6; dn[6] += e6;
            sex[wid][7][lane] = e7; dn[7] += e7;
        }
        __syncwarp();
        int n = min(32, end - base);
#pragma unroll 4
        for (int j = 0; j < n; j++) {
            int s = __shfl_sync(0xffffffffu, sc, j);
            float a = sex[wid][h][j];
            float4 v = *(const float4*)&g_h1[s * 128 + lane * 4];
            acc.x += a * v.x; acc.y += a * v.y;
            acc.z += a * v.z; acc.w += a * v.w;
        }
        __syncwarp();
    }

#pragma unroll
    for (int hh = 0; hh < 8; hh++)
        for (int off = 16; off; off >>= 1)
            dn[hh] += __shfl_xor_sync(0xffffffffu, dn[hh], off);
    float rdn = 1.f / (dn[h] + 1e-16f);

    float4 bb = *(const float4*)&b1[lane * 4];
    acc.x = acc.x * rdn + bb.x;
    acc.y = acc.y * rdn + bb.y;
    acc.z = acc.z * rdn + bb.z;
    acc.w = acc.w * rdn + bb.w;
    acc.x = acc.x > 0.f ? acc.x : expm1f(acc.x);
    acc.y = acc.y > 0.f ? acc.y : expm1f(acc.y);
    acc.z = acc.z > 0.f ? acc.z : expm1f(acc.z);
    acc.w = acc.w > 0.f ? acc.w : expm1f(acc.w);
    *(float4*)&g_o1[w * 128 + lane * 4] = acc;
}

// ==================== GEMM2 (128->40, LDS.128 f32x2) with fused a2 dots ====================
__global__ void gemm2_kernel(const float* __restrict__ W,
                             const float* __restrict__ atts, const float* __restrict__ attd) {
    extern __shared__ float sm[];
    float* xs = sm + 5120;           // 64*132
    float* sa = sm + 5120 + 8448;    // 64
    float* sd = sa + 64;             // 64
    int t = threadIdx.x;
    int ct = t % 10, rt = t / 10;
    int row0 = blockIdx.x * 64;

    for (int i = t; i < 5120; i += 160) {   // pack W: [kpp][e][q][kk]
        int k = i / 40, c = i % 40;
        sm[(k >> 2) * 160 + (c & 3) * 40 + (c >> 2) * 4 + (k & 3)] = W[i];
    }
    for (int i = t; i < 2048; i += 160) {
        int r = i >> 5, k4 = (i & 31) * 4;
        int row = row0 + r;
        float4 v = (row < NN) ? *(const float4*)&g_o1[row * 128 + k4]
                              : make_float4(0.f, 0.f, 0.f, 0.f);
        *(float4*)&xs[r * 132 + k4] = v;
    }
    if (t < 64) { sa[t] = 0.f; sd[t] = 0.f; }
    __syncthreads();

    u64 acc2[4][4];
#pragma unroll
    for (int i = 0; i < 4; i++)
#pragma unroll
        for (int c = 0; c < 4; c++) acc2[i][c] = 0ull;

#pragma unroll 2
    for (int kpp = 0; kpp < 32; kpp++) {
        const float* wb = sm + kpp * 160 + 4 * ct;
        ulonglong2 w0 = *(const ulonglong2*)(wb);
        ulonglong2 w1 = *(const ulonglong2*)(wb + 40);
        ulonglong2 w2 = *(const ulonglong2*)(wb + 80);
        ulonglong2 w3 = *(const ulonglong2*)(wb + 120);
#pragma unroll
        for (int i = 0; i < 4; i++) {
            ulonglong2 xp = *(const ulonglong2*)&xs[(rt * 4 + i) * 132 + 4 * kpp];
            ffma2(acc2[i][0], xp.x, w0.x); ffma2(acc2[i][0], xp.y, w0.y);
            ffma2(acc2[i][1], xp.x, w1.x); ffma2(acc2[i][1], xp.y, w1.y);
            ffma2(acc2[i][2], xp.x, w2.x); ffma2(acc2[i][2], xp.y, w2.y);
            ffma2(acc2[i][3], xp.x, w3.x); ffma2(acc2[i][3], xp.y, w3.y);
        }
    }

    float4 avs = *(const float4*)&atts[4 * ct];
    float4 avd = *(const float4*)&attd[4 * ct];
#pragma unroll
    for (int i = 0; i < 4; i++) {
        float a[4];
#pragma unroll
        for (int c = 0; c < 4; c++) {
            float lo, hi; upk2(lo, hi, acc2[i][c]);
            a[c] = lo + hi;
        }
        int row = row0 + rt * 4 + i;
        if (row < NN)
            *(float4*)&g_z[row * 40 + 4 * ct] = make_float4(a[0], a[1], a[2], a[3]);
        float ps = a[0] * avs.x + a[1] * avs.y + a[2] * avs.z + a[3] * avs.w;
        float pd = a[0] * avd.x + a[1] * avd.y + a[2] * avd.z + a[3] * avd.w;
        atomicAdd(&sa[rt * 4 + i], ps);
        atomicAdd(&sd[rt * 4 + i], pd);
    }
    __syncthreads();
    if (t < 64) {
        int row = row0 + t;
        if (row < NN) { g_as2[row] = sa[t]; g_ad2[row] = sd[t]; }
    }
}

// ==================== fused layer2: single-pass + bias + log_softmax (R7 form) ====================
__global__ void l2_gather(float* __restrict__ out, const float* __restrict__ b2) {
    int w = (blockIdx.x * blockDim.x + threadIdx.x) >> 5;
    int lane = threadIdx.x & 31;
    if (w >= NN) return;
    int beg = g_rp[w], end = g_rp[w + 1];
    float adw = g_ad2[w];

    float dn = 0.f;
    float a1 = 0.f, a2 = 0.f;
    for (int base = beg; base < end; base += 32) {
        int idx = base + lane;
        int sc = (idx < end) ? g_col[idx] : 0;
        float ex = (idx < end) ? __expf(lrelu(g_as2[sc] + adw)) : 0.f;
        dn += ex;
        int n = min(32, end - base);
#pragma unroll 4
        for (int j = 0; j < n; j++) {
            float al = __shfl_sync(0xffffffffu, ex, j);
            int s = __shfl_sync(0xffffffffu, sc, j);
            a1 += al * g_z[s * 40 + lane];
            if (lane < 8) a2 += al * g_z[s * 40 + 32 + lane];
        }
    }
    for (int off = 16; off; off >>= 1)
        dn += __shfl_xor_sync(0xffffffffu, dn, off);
    float rdn = 1.f / (dn + 1e-16f);

    float v1 = a1 * rdn + b2[lane];
    float v2 = (lane < 8) ? a2 * rdn + b2[32 + lane] : -1e30f;
    float m = fmaxf(v1, v2);
    for (int o = 16; o; o >>= 1) m = fmaxf(m, __shfl_xor_sync(0xffffffffu, m, o));
    float s = expf(v1 - m) + ((lane < 8) ? expf(v2 - m) : 0.f);
    for (int o = 16; o; o >>= 1) s += __shfl_xor_sync(0xffffffffu, s, o);
    float ls = m + logf(s);
    out[w * 40 + lane] = v1 - ls;
    if (lane < 8) out[w * 40 + 32 + lane] = v2 - ls;
}

// ==================== launch ====================
extern "C" void kernel_launch(void* const* d_in, const int* in_sizes, int n_in,
                              void* d_out, int out_size) {
    const float* x   = (const float*)d_in[0];
    const int*   ei  = (const int*)d_in[1];
    const float* W1  = (const float*)d_in[2];
    const float* as1 = (const float*)d_in[3];
    const float* ad1 = (const float*)d_in[4];
    const float* b1  = (const float*)d_in[5];
    const float* W2  = (const float*)d_in[6];
    const float* as2 = (const float*)d_in[7];
    const float* ad2 = (const float*)d_in[8];
    const float* b2  = (const float*)d_in[9];
    float* out = (float*)d_out;

    static cudaStream_t sB = nullptr;
    static cudaEvent_t evF = nullptr, evJ = nullptr;
    if (!sB) {
        cudaStreamCreateWithFlags(&sB, cudaStreamNonBlocking);
        cudaEventCreateWithFlags(&evF, cudaEventDisableTiming);
        cudaEventCreateWithFlags(&evJ, cudaEventDisableTiming);
    }

    const int SM1 = (16384 + 64 * 132) * 4;          // 99328 B
    const int SM2 = (5120 + 64 * 132 + 128) * 4;     // 54784 B
    cudaFuncSetAttribute(gemm1_kernel, cudaFuncAttributeMaxDynamicSharedMemorySize, SM1);
    cudaFuncSetAttribute(gemm2_kernel, cudaFuncAttributeMaxDynamicSharedMemorySize, SM2);

    // fork: CSR build on side stream, gemm1 on main stream (R7 structure).
    cudaEventRecord(evF, 0);
    cudaStreamWaitEvent(sB, evF, 0);

    hist_kernel<<<(ET + 255) / 256, 256, 0, sB>>>(ei);   // 0
    scan1<<<NB, 1024, 0, sB>>>();                        // 1
    scan2<<<1, 128, 0, sB>>>();                          // 2
    gemm1_kernel<<<(NN + 63) / 64, 256, SM1>>>(x, W1, as1, ad1);   // 3 <- profiled
    scan3<<<(NN + 255) / 256, 256, 0, sB>>>();           // 4
    scatter<<<(ET + 255) / 256, 256, 0, sB>>>(ei);       // 5
    cudaEventRecord(evJ, sB);

    cudaStreamWaitEvent(0, evJ, 0);

    l1_gather<<<(NN * 32 + 255) / 256, 256>>>(b1);       // 6
    gemm2_kernel<<<(NN + 63) / 64, 160, SM2>>>(W2, as2, ad2);  // 7
    l2_gather<<<(NN * 32 + 255) / 256, 256>>>(out, b2);  // 8
}

// round 12
// speedup vs baseline: 1.1419x; 1.0442x over previous
#include <cuda_runtime.h>
#include <cuda_bf16.h>
#include <cstdint>

#define NN 100000
#define NE 1600000
#define ET (NE + NN)
#define NB 98   // ceil(NN/1024) scan blocks

typedef unsigned long long u64;

// -------- scratch (device globals: no allocations allowed) --------
__device__ int   g_col[ET];
__device__ int   g_deg[NN];
__device__ int   g_scan[NN];
__device__ int   g_bsum[NB];
__device__ int   g_boff[NB];
__device__ int   g_rp[NN + 1];
__device__ int   g_cur[NN];
__device__ uint4 g_wt_hi[2048];   // W1^T bf16 hi, linear [n][k] (128x128)
__device__ uint4 g_wt_lo[2048];   // W1^T bf16 lo
__device__ float g_h1[NN * 128];
__device__ float g_as1[NN * 8];
__device__ float g_ad1[NN * 8];
__device__ float g_o1[NN * 128];
__device__ float g_z[NN * 40];
__device__ float g_as2[NN];
__device__ float g_ad2[NN];

__device__ __forceinline__ float lrelu(float v) { return v > 0.f ? v : 0.2f * v; }

__device__ __forceinline__ void ffma2(u64& d, u64 a, u64 b) {
    asm("fma.rn.f32x2 %0, %1, %2, %0;" : "+l"(d) : "l"(a), "l"(b));
}
__device__ __forceinline__ void upk2(float& lo, float& hi, u64 v) {
    asm("mov.b64 {%0, %1}, %2;" : "=f"(lo), "=f"(hi) : "l"(v));
}
__device__ __forceinline__ int detect64(const int* e32) {
    int z = 0;
#pragma unroll
    for (int j = 1; j <= 16; j++) z |= e32[2 * j + 1];
    return (z == 0) ? 1 : 0;
}

// mma.sync m16n8k16 row.col f32.bf16.bf16.f32 (baseline PTX, works on sm_103)
__device__ __forceinline__ void mma16816(float* d, const uint32_t* a, const uint32_t* b) {
    asm volatile(
        "mma.sync.aligned.m16n8k16.row.col.f32.bf16.bf16.f32 "
        "{%0,%1,%2,%3}, {%4,%5,%6,%7}, {%8,%9}, {%0,%1,%2,%3};"
        : "+f"(d[0]), "+f"(d[1]), "+f"(d[2]), "+f"(d[3])
        : "r"(a[0]), "r"(a[1]), "r"(a[2]), "r"(a[3]), "r"(b[0]), "r"(b[1]));
}

// ==================== CSR build ====================
__global__ void hist_kernel(const int* __restrict__ e32) {
    __shared__ int is64;
    if (threadIdx.x == 0) is64 = detect64(e32);
    __syncthreads();
    int i = blockIdx.x * blockDim.x + threadIdx.x;
    if (i >= ET) return;
    int d;
    if (i < NE) d = is64 ? e32[2 * (NE + i)] : e32[NE + i];
    else        d = i - NE;
    atomicAdd(&g_deg[d], 1);
}

__global__ void scan1() {
    __shared__ int sm[1024];
    int i = blockIdx.x * 1024 + threadIdx.x;
    int v = (i < NN) ? g_deg[i] : 0;
    sm[threadIdx.x] = v;
    __syncthreads();
    for (int off = 1; off < 1024; off <<= 1) {
        int t = (threadIdx.x >= off) ? sm[threadIdx.x - off] : 0;
        __syncthreads();
        sm[threadIdx.x] += t;
        __syncthreads();
    }
    if (i < NN) g_scan[i] = sm[threadIdx.x];
    if (threadIdx.x == 1023) g_bsum[blockIdx.x] = sm[1023];
}

__global__ void scan2() {
    __shared__ int sm[128];
    int t = threadIdx.x;
    int v = (t < NB) ? g_bsum[t] : 0;
    sm[t] = v;
    __syncthreads();
    for (int off = 1; off < 128; off <<= 1) {
        int a = (t >= off) ? sm[t - off] : 0;
        __syncthreads();
        sm[t] += a;
        __syncthreads();
    }
    if (t < NB) g_boff[t] = sm[t] - v;
}

__global__ void scan3() {
    int i = blockIdx.x * blockDim.x + threadIdx.x;
    if (i >= NN) return;
    int incl = g_scan[i] + g_boff[i >> 10];
    g_rp[i + 1] = incl;
    g_cur[i] = incl - g_deg[i];
    if (i == 0) g_rp[0] = 0;
}

__global__ void scatter(const int* __restrict__ e32) {
    __shared__ int is64;
    if (threadIdx.x == 0) is64 = detect64(e32);
    __syncthreads();
    int i = blockIdx.x * blockDim.x + threadIdx.x;
    if (i < NN) g_deg[i] = 0;
    if (i >= ET) return;
    int s, d;
    if (i < NE) {
        if (is64) { s = e32[2 * i]; d = e32[2 * (NE + i)]; }
        else      { s = e32[i];     d = e32[NE + i]; }
    } else {
        s = d = i - NE;
    }
    int pos = atomicAdd(&g_cur[d], 1);
    g_col[pos] = s;
}

// ==================== w_prep: W1^T -> bf16 hi/lo, linear [n][k] ====================
__global__ void w_prep(const float* __restrict__ W) {
    int i = blockIdx.x * blockDim.x + threadIdx.x;
    if (i >= 128 * 32) return;
    int n = i >> 5, k4 = (i & 31) * 4;
    float v0 = W[(k4 + 0) * 128 + n];
    float v1 = W[(k4 + 1) * 128 + n];
    float v2 = W[(k4 + 2) * 128 + n];
    float v3 = W[(k4 + 3) * 128 + n];
    __nv_bfloat162 h01 = __floats2bfloat162_rn(v0, v1);
    __nv_bfloat162 h23 = __floats2bfloat162_rn(v2, v3);
    __nv_bfloat162 l01 = __floats2bfloat162_rn(v0 - __low2float(h01), v1 - __high2float(h01));
    __nv_bfloat162 l23 = __floats2bfloat162_rn(v2 - __low2float(h23), v3 - __high2float(h23));
    uint32_t* hi = (uint32_t*)g_wt_hi;
    uint32_t* lo = (uint32_t*)g_wt_lo;
    int w32 = (n * 128 + k4) >> 1;    // 32-bit word index
    hi[w32] = *(uint32_t*)&h01; hi[w32 + 1] = *(uint32_t*)&h23;
    lo[w32] = *(uint32_t*)&l01; lo[w32 + 1] = *(uint32_t*)&l23;
}

// ==================== GEMM1 via mma.sync: h1 = x @ W1 + attention dots ====================
// 256 threads, 128 rows/CTA; warp w computes rows w*16..w*16+15, all 128 cols.
// smem tiles bf16 [row][k], row stride 136 (conflict-free for fragment pattern).
#define XSTR 136
#define SM_ATT 0
#define SM_ATD 512
#define SM_XHI 1024
#define SM_XLO (1024 + 34816)
#define SM_WHI (1024 + 69632)
#define SM_WLO (1024 + 104448)
#define G1_SMEM (1024 + 139264)

__global__ void __launch_bounds__(256, 1)
gemm1_tc(const float* __restrict__ x, const float* __restrict__ atts, const float* __restrict__ attd) {
    extern __shared__ char smem[];
    int t = threadIdx.x, lane = t & 31, wid = t >> 5;
    int row0 = blockIdx.x * 128;

    if (t < 128) {
        ((float*)(smem + SM_ATT))[t] = atts[t];
        ((float*)(smem + SM_ATD))[t] = attd[t];
    }

    // x tile -> bf16 hi/lo
    for (int i = t; i < 4096; i += 256) {
        int r = i >> 5, c4 = (i & 31) * 4;
        int row = row0 + r;
        float4 v = (row < NN) ? *(const float4*)&x[row * 128 + c4]
                              : make_float4(0.f, 0.f, 0.f, 0.f);
        __nv_bfloat162 h01 = __floats2bfloat162_rn(v.x, v.y);
        __nv_bfloat162 h23 = __floats2bfloat162_rn(v.z, v.w);
        __nv_bfloat162 l01 = __floats2bfloat162_rn(v.x - __low2float(h01), v.y - __high2float(h01));
        __nv_bfloat162 l23 = __floats2bfloat162_rn(v.z - __low2float(h23), v.w - __high2float(h23));
        int off = (r * XSTR + c4) * 2;
        *(uint32_t*)(smem + SM_XHI + off)     = *(uint32_t*)&h01;
        *(uint32_t*)(smem + SM_XHI + off + 4) = *(uint32_t*)&h23;
        *(uint32_t*)(smem + SM_XLO + off)     = *(uint32_t*)&l01;
        *(uint32_t*)(smem + SM_XLO + off + 4) = *(uint32_t*)&l23;
    }
    // W^T tiles: linear gmem -> strided smem
    for (int i = t; i < 2048; i += 256) {
        int n = i >> 4, k8 = (i & 15) * 8;
        int off = (n * XSTR + k8) * 2;
        *(uint4*)(smem + SM_WHI + off) = g_wt_hi[i];
        *(uint4*)(smem + SM_WLO + off) = g_wt_lo[i];
    }
    __syncthreads();

    int q = lane >> 2, c2 = (lane & 3) * 2;
    int wrow = wid * 16;

    float acc[16][4];
#pragma unroll
    for (int nt = 0; nt < 16; nt++)
#pragma unroll
        for (int j = 0; j < 4; j++) acc[nt][j] = 0.f;

#pragma unroll
    for (int ks = 0; ks < 8; ks++) {
        int abase = ((wrow + q) * XSTR + ks * 16 + c2) * 2;
        uint32_t ah[4], al[4];
        ah[0] = *(uint32_t*)(smem + SM_XHI + abase);
        ah[1] = *(uint32_t*)(smem + SM_XHI + abase + 8 * XSTR * 2);
        ah[2] = *(uint32_t*)(smem + SM_XHI + abase + 16);
        ah[3] = *(uint32_t*)(smem + SM_XHI + abase + 8 * XSTR * 2 + 16);
        al[0] = *(uint32_t*)(smem + SM_XLO + abase);
        al[1] = *(uint32_t*)(smem + SM_XLO + abase + 8 * XSTR * 2);
        al[2] = *(uint32_t*)(smem + SM_XLO + abase + 16);
        al[3] = *(uint32_t*)(smem + SM_XLO + abase + 8 * XSTR * 2 + 16);
#pragma unroll
        for (int nt = 0; nt < 16; nt++) {
            int bbase = ((nt * 8 + q) * XSTR + ks * 16 + c2) * 2;
            uint32_t bh[2], bl[2];
            bh[0] = *(uint32_t*)(smem + SM_WHI + bbase);
            bh[1] = *(uint32_t*)(smem + SM_WHI + bbase + 16);
            bl[0] = *(uint32_t*)(smem + SM_WLO + bbase);
            bl[1] = *(uint32_t*)(smem + SM_WLO + bbase + 16);
            mma16816(acc[nt], ah, bh);
            mma16816(acc[nt], ah, bl);
            mma16816(acc[nt], al, bh);
        }
    }

    // epilogue: store h1, compute per-head attention dots, quad-reduce
    const float* satt = (const float*)(smem + SM_ATT);
    const float* satd = (const float*)(smem + SM_ATD);
    int rowA = row0 + wrow + q;
    int rowB = rowA + 8;
    float psA[8], pdA[8], psB[8], pdB[8];
#pragma unroll
    for (int h = 0; h < 8; h++) { psA[h] = pdA[h] = psB[h] = pdB[h] = 0.f; }

#pragma unroll
    for (int nt = 0; nt < 16; nt++) {
        int col = nt * 8 + c2;
        int h = nt >> 1;
        float d0 = acc[nt][0], d1 = acc[nt][1], d2 = acc[nt][2], d3 = acc[nt][3];
        float t0 = satt[col], t1 = satt[col + 1];
        float u0 = satd[col], u1 = satd[col + 1];
        psA[h] += d0 * t0 + d1 * t1; pdA[h] += d0 * u0 + d1 * u1;
        psB[h] += d2 * t0 + d3 * t1; pdB[h] += d2 * u0 + d3 * u1;
        if (rowA < NN) *(float2*)&g_h1[rowA * 128 + col] = make_float2(d0, d1);
        if (rowB < NN) *(float2*)&g_h1[rowB * 128 + col] = make_float2(d2, d3);
    }
#pragma unroll
    for (int h = 0; h < 8; h++) {
        psA[h] += __shfl_xor_sync(0xffffffffu, psA[h], 1);
        psA[h] += __shfl_xor_sync(0xffffffffu, psA[h], 2);
        pdA[h] += __shfl_xor_sync(0xffffffffu, pdA[h], 1);
        pdA[h] += __shfl_xor_sync(0xffffffffu, pdA[h], 2);
        psB[h] += __shfl_xor_sync(0xffffffffu, psB[h], 1);
        psB[h] += __shfl_xor_sync(0xffffffffu, psB[h], 2);
        pdB[h] += __shfl_xor_sync(0xffffffffu, pdB[h], 1);
        pdB[h] += __shfl_xor_sync(0xffffffffu, pdB[h], 2);
    }
    int c = lane & 3;   // lane c writes heads c and c+4
#pragma unroll
    for (int u = 0; u < 2; u++) {
        int h = c + u * 4;
        if (rowA < NN) { g_as1[rowA * 8 + h] = psA[h]; g_ad1[rowA * 8 + h] = pdA[h]; }
        if (rowB < NN) { g_as1[rowB * 8 + h] = psB[h]; g_ad1[rowB * 8 + h] = pdB[h]; }
    }
}

// ==================== fused layer1: single-pass, bank-conflict-free staging ====================
__global__ void l1_gather(const float* __restrict__ b1) {
    __shared__ float sex[8][8][33];
    int w = (blockIdx.x * blockDim.x + threadIdx.x) >> 5;
    int wid = (threadIdx.x >> 5) & 7;
    int lane = threadIdx.x & 31;
    if (w >= NN) return;
    int beg = g_rp[w], end = g_rp[w + 1];

    float4 ad0 = *(const float4*)&g_ad1[w * 8];
    float4 ad1v = *(const float4*)&g_ad1[w * 8 + 4];

    int h = lane >> 2;
    float dn[8] = {};
    float4 acc = make_float4(0.f, 0.f, 0.f, 0.f);

    for (int base = beg; base < end; base += 32) {
        int idx = base + lane;
        int sc = (idx < end) ? g_col[idx] : 0;
        float msk = (idx < end) ? 1.f : 0.f;
        {
            float4 s0 = *(const float4*)&g_as1[sc * 8];
            float4 s1 = *(const float4*)&g_as1[sc * 8 + 4];
            float e0 = __expf(lrelu(s0.x + ad0.x)) * msk;
            float e1 = __expf(lrelu(s0.y + ad0.y)) * msk;
            float e2 = __expf(lrelu(s0.z + ad0.z)) * msk;
            float e3 = __expf(lrelu(s0.w + ad0.w)) * msk;
            float e4 = __expf(lrelu(s1.x + ad1v.x)) * msk;
            float e5 = __expf(lrelu(s1.y + ad1v.y)) * msk;
            float e6 = __expf(lrelu(s1.z + ad1v.z)) * msk;
            float e7 = __expf(lrelu(s1.w + ad1v.w)) * msk;
            sex[wid][0][lane] = e0; dn[0] += e0;
            sex[wid][1][lane] = e1; dn[1] += e1;
            sex[wid][2][lane] = e2; dn[2] += e2;
            sex[wid][3][lane] = e3; dn[3] += e3;
            sex[wid][4][lane] = e4; dn[4] += e4;
            sex[wid][5][lane] = e5; dn[5] += e5;
            sex[wid][6][lane] = e6; dn[6] += e6;
            sex[wid][7][lane] = e7; dn[7] += e7;
        }
        __syncwarp();
        int n = min(32, end - base);
#pragma unroll 4
        for (int j = 0; j < n; j++) {
            int s = __shfl_sync(0xffffffffu, sc, j);
            float a = sex[wid][h][j];
            float4 v = *(const float4*)&g_h1[s * 128 + lane * 4];
            acc.x += a * v.x; acc.y += a * v.y;
            acc.z += a * v.z; acc.w += a * v.w;
        }
        __syncwarp();
    }

#pragma unroll
    for (int hh = 0; hh < 8; hh++)
        for (int off = 16; off; off >>= 1)
            dn[hh] += __shfl_xor_sync(0xffffffffu, dn[hh], off);
    float rdn = 1.f / (dn[h] + 1e-16f);

    float4 bb = *(const float4*)&b1[lane * 4];
    acc.x = acc.x * rdn + bb.x;
    acc.y = acc.y * rdn + bb.y;
    acc.z = acc.z * rdn + bb.z;
    acc.w = acc.w * rdn + bb.w;
    acc.x = acc.x > 0.f ? acc.x : expm1f(acc.x);
    acc.y = acc.y > 0.f ? acc.y : expm1f(acc.y);
    acc.z = acc.z > 0.f ? acc.z : expm1f(acc.z);
    acc.w = acc.w > 0.f ? acc.w : expm1f(acc.w);
    *(float4*)&g_o1[w * 128 + lane * 4] = acc;
}

// ==================== GEMM2 (128->40, LDS.128 f32x2) with fused a2 dots ====================
__global__ void gemm2_kernel(const float* __restrict__ W,
                             const float* __restrict__ atts, const float* __restrict__ attd) {
    extern __shared__ float sm[];
    float* xs = sm + 5120;
    float* sa = sm + 5120 + 8448;
    float* sd = sa + 64;
    int t = threadIdx.x;
    int ct = t % 10, rt = t / 10;
    int row0 = blockIdx.x * 64;

    for (int i = t; i < 5120; i += 160) {
        int k = i / 40, c = i % 40;
        sm[(k >> 2) * 160 + (c & 3) * 40 + (c >> 2) * 4 + (k & 3)] = W[i];
    }
    for (int i = t; i < 2048; i += 160) {
        int r = i >> 5, k4 = (i & 31) * 4;
        int row = row0 + r;
        float4 v = (row < NN) ? *(const float4*)&g_o1[row * 128 + k4]
                              : make_float4(0.f, 0.f, 0.f, 0.f);
        *(float4*)&xs[r * 132 + k4] = v;
    }
    if (t < 64) { sa[t] = 0.f; sd[t] = 0.f; }
    __syncthreads();

    u64 acc2[4][4];
#pragma unroll
    for (int i = 0; i < 4; i++)
#pragma unroll
        for (int c = 0; c < 4; c++) acc2[i][c] = 0ull;

#pragma unroll 2
    for (int kpp = 0; kpp < 32; kpp++) {
        const float* wb = sm + kpp * 160 + 4 * ct;
        ulonglong2 w0 = *(const ulonglong2*)(wb);
        ulonglong2 w1 = *(const ulonglong2*)(wb + 40);
        ulonglong2 w2 = *(const ulonglong2*)(wb + 80);
        ulonglong2 w3 = *(const ulonglong2*)(wb + 120);
#pragma unroll
        for (int i = 0; i < 4; i++) {
            ulonglong2 xp = *(const ulonglong2*)&xs[(rt * 4 + i) * 132 + 4 * kpp];
            ffma2(acc2[i][0], xp.x, w0.x); ffma2(acc2[i][0], xp.y, w0.y);
            ffma2(acc2[i][1], xp.x, w1.x); ffma2(acc2[i][1], xp.y, w1.y);
            ffma2(acc2[i][2], xp.x, w2.x); ffma2(acc2[i][2], xp.y, w2.y);
            ffma2(acc2[i][3], xp.x, w3.x); ffma2(acc2[i][3], xp.y, w3.y);
        }
    }

    float4 avs = *(const float4*)&atts[4 * ct];
    float4 avd = *(const float4*)&attd[4 * ct];
#pragma unroll
    for (int i = 0; i < 4; i++) {
        float a[4];
#pragma unroll
        for (int c = 0; c < 4; c++) {
            float lo, hi; upk2(lo, hi, acc2[i][c]);
            a[c] = lo + hi;
        }
        int row = row0 + rt * 4 + i;
        if (row < NN)
            *(float4*)&g_z[row * 40 + 4 * ct] = make_float4(a[0], a[1], a[2], a[3]);
        float ps = a[0] * avs.x + a[1] * avs.y + a[2] * avs.z + a[3] * avs.w;
        float pd = a[0] * avd.x + a[1] * avd.y + a[2] * avd.z + a[3] * avd.w;
        atomicAdd(&sa[rt * 4 + i], ps);
        atomicAdd(&sd[rt * 4 + i], pd);
    }
    __syncthreads();
    if (t < 64) {
        int row = row0 + t;
        if (row < NN) { g_as2[row] = sa[t]; g_ad2[row] = sd[t]; }
    }
}

// ==================== fused layer2: single-pass + bias + log_softmax ====================
__global__ void l2_gather(float* __restrict__ out, const float* __restrict__ b2) {
    int w = (blockIdx.x * blockDim.x + threadIdx.x) >> 5;
    int lane = threadIdx.x & 31;
    if (w >= NN) return;
    int beg = g_rp[w], end = g_rp[w + 1];
    float adw = g_ad2[w];

    float dn = 0.f;
    float a1 = 0.f, a2 = 0.f;
    for (int base = beg; base < end; base += 32) {
        int idx = base + lane;
        int sc = (idx < end) ? g_col[idx] : 0;
        float ex = (idx < end) ? __expf(lrelu(g_as2[sc] + adw)) : 0.f;
        dn += ex;
        int n = min(32, end - base);
#pragma unroll 4
        for (int j = 0; j < n; j++) {
            float al = __shfl_sync(0xffffffffu, ex, j);
            int s = __shfl_sync(0xffffffffu, sc, j);
            a1 += al * g_z[s * 40 + lane];
            if (lane < 8) a2 += al * g_z[s * 40 + 32 + lane];
        }
    }
    for (int off = 16; off; off >>= 1)
        dn += __shfl_xor_sync(0xffffffffu, dn, off);
    float rdn = 1.f / (dn + 1e-16f);

    float v1 = a1 * rdn + b2[lane];
    float v2 = (lane < 8) ? a2 * rdn + b2[32 + lane] : -1e30f;
    float m = fmaxf(v1, v2);
    for (int o = 16; o; o >>= 1) m = fmaxf(m, __shfl_xor_sync(0xffffffffu, m, o));
    float s = expf(v1 - m) + ((lane < 8) ? expf(v2 - m) : 0.f);
    for (int o = 16; o; o >>= 1) s += __shfl_xor_sync(0xffffffffu, s, o);
    float ls = m + logf(s);
    out[w * 40 + lane] = v1 - ls;
    if (lane < 8) out[w * 40 + 32 + lane] = v2 - ls;
}

// ==================== launch ====================
extern "C" void kernel_launch(void* const* d_in, const int* in_sizes, int n_in,
                              void* d_out, int out_size) {
    const float* x   = (const float*)d_in[0];
    const int*   ei  = (const int*)d_in[1];
    const float* W1  = (const float*)d_in[2];
    const float* as1 = (const float*)d_in[3];
    const float* ad1 = (const float*)d_in[4];
    const float* b1  = (const float*)d_in[5];
    const float* W2  = (const float*)d_in[6];
    const float* as2 = (const float*)d_in[7];
    const float* ad2 = (const float*)d_in[8];
    const float* b2  = (const float*)d_in[9];
    float* out = (float*)d_out;

    static cudaStream_t sB = nullptr;
    static cudaEvent_t evF = nullptr, evJ = nullptr;
    if (!sB) {
        cudaStreamCreateWithFlags(&sB, cudaStreamNonBlocking);
        cudaEventCreateWithFlags(&evF, cudaEventDisableTiming);
        cudaEventCreateWithFlags(&evJ, cudaEventDisableTiming);
    }

    const int SM2 = (5120 + 64 * 132 + 128) * 4;
    cudaFuncSetAttribute(gemm1_tc, cudaFuncAttributeMaxDynamicSharedMemorySize, G1_SMEM);
    cudaFuncSetAttribute(gemm2_kernel, cudaFuncAttributeMaxDynamicSharedMemorySize, SM2);

    // fork: CSR build on side stream; W-prep + tensor-core gemm1 on main stream.
    cudaEventRecord(evF, 0);
    cudaStreamWaitEvent(sB, evF, 0);

    w_prep<<<16, 256>>>(W1);                                   // 0 (main)
    hist_kernel<<<(ET + 255) / 256, 256, 0, sB>>>(ei);         // 1
    scan1<<<NB, 1024, 0, sB>>>();                              // 2
    gemm1_tc<<<(NN + 127) / 128, 256, G1_SMEM>>>(x, as1, ad1); // 3 <- profiled
    scan2<<<1, 128, 0, sB>>>();                                // 4
    scan3<<<(NN + 255) / 256, 256, 0, sB>>>();                 // 5
    scatter<<<(ET + 255) / 256, 256, 0, sB>>>(ei);             // 6
    cudaEventRecord(evJ, sB);

    cudaStreamWaitEvent(0, evJ, 0);

    l1_gather<<<(NN * 32 + 255) / 256, 256>>>(b1);
    gemm2_kernel<<<(NN + 63) / 64, 160, SM2>>>(W2, as2, ad2);
    l2_gather<<<(NN * 32 + 255) / 256, 256>>>(out, b2);
}

// round 13
// speedup vs baseline: 1.2069x; 1.0569x over previous
#include <cuda_runtime.h>
#include <cuda_bf16.h>
#include <cstdint>

#define NN 100000
#define NE 1600000
#define ET (NE + NN)
#define NB 98   // ceil(NN/1024) scan blocks

typedef unsigned long long u64;

// -------- scratch (device globals: no allocations allowed) --------
__device__ int   g_col[ET];
__device__ int   g_deg[NN];
__device__ int   g_scan[NN];
__device__ int   g_bsum[NB];
__device__ int   g_boff[NB];
__device__ int   g_rp[NN + 1];
__device__ int   g_cur[NN];
__device__ uint4 g_wt_hi[2048];   // W1^T bf16 hi, linear [n][k] (128x128)
__device__ uint4 g_wt_lo[2048];   // W1^T bf16 lo
__device__ float g_h1[NN * 128];
__device__ float g_as1[NN * 8];
__device__ float g_ad1[NN * 8];
__device__ float g_o1[NN * 128];
__device__ float g_z[NN * 40];
__device__ float g_as2[NN];
__device__ float g_ad2[NN];

__device__ __forceinline__ float lrelu(float v) { return v > 0.f ? v : 0.2f * v; }

__device__ __forceinline__ void ffma2(u64& d, u64 a, u64 b) {
    asm("fma.rn.f32x2 %0, %1, %2, %0;" : "+l"(d) : "l"(a), "l"(b));
}
__device__ __forceinline__ void upk2(float& lo, float& hi, u64 v) {
    asm("mov.b64 {%0, %1}, %2;" : "=f"(lo), "=f"(hi) : "l"(v));
}
__device__ __forceinline__ int detect64(const int* e32) {
    int z = 0;
#pragma unroll
    for (int j = 1; j <= 16; j++) z |= e32[2 * j + 1];
    return (z == 0) ? 1 : 0;
}

// mma.sync m16n8k16 row.col f32.bf16.bf16.f32 (baseline PTX, works on sm_103)
__device__ __forceinline__ void mma16816(float* d, const uint32_t* a, const uint32_t* b) {
    asm volatile(
        "mma.sync.aligned.m16n8k16.row.col.f32.bf16.bf16.f32 "
        "{%0,%1,%2,%3}, {%4,%5,%6,%7}, {%8,%9}, {%0,%1,%2,%3};"
        : "+f"(d[0]), "+f"(d[1]), "+f"(d[2]), "+f"(d[3])
        : "r"(a[0]), "r"(a[1]), "r"(a[2]), "r"(a[3]), "r"(b[0]), "r"(b[1]));
}

// ==================== CSR build ====================
__global__ void hist_kernel(const int* __restrict__ e32) {
    __shared__ int is64;
    if (threadIdx.x == 0) is64 = detect64(e32);
    __syncthreads();
    int i = blockIdx.x * blockDim.x + threadIdx.x;
    if (i >= ET) return;
    int d;
    if (i < NE) d = is64 ? e32[2 * (NE + i)] : e32[NE + i];
    else        d = i - NE;
    atomicAdd(&g_deg[d], 1);
}

__global__ void scan1() {
    __shared__ int sm[1024];
    int i = blockIdx.x * 1024 + threadIdx.x;
    int v = (i < NN) ? g_deg[i] : 0;
    sm[threadIdx.x] = v;
    __syncthreads();
    for (int off = 1; off < 1024; off <<= 1) {
        int t = (threadIdx.x >= off) ? sm[threadIdx.x - off] : 0;
        __syncthreads();
        sm[threadIdx.x] += t;
        __syncthreads();
    }
    if (i < NN) g_scan[i] = sm[threadIdx.x];
    if (threadIdx.x == 1023) g_bsum[blockIdx.x] = sm[1023];
}

__global__ void scan2() {
    __shared__ int sm[128];
    int t = threadIdx.x;
    int v = (t < NB) ? g_bsum[t] : 0;
    sm[t] = v;
    __syncthreads();
    for (int off = 1; off < 128; off <<= 1) {
        int a = (t >= off) ? sm[t - off] : 0;
        __syncthreads();
        sm[t] += a;
        __syncthreads();
    }
    if (t < NB) g_boff[t] = sm[t] - v;
}

__global__ void scan3() {
    int i = blockIdx.x * blockDim.x + threadIdx.x;
    if (i >= NN) return;
    int incl = g_scan[i] + g_boff[i >> 10];
    g_rp[i + 1] = incl;
    g_cur[i] = incl - g_deg[i];
    if (i == 0) g_rp[0] = 0;
}

__global__ void scatter(const int* __restrict__ e32) {
    __shared__ int is64;
    if (threadIdx.x == 0) is64 = detect64(e32);
    __syncthreads();
    int i = blockIdx.x * blockDim.x + threadIdx.x;
    if (i < NN) g_deg[i] = 0;
    if (i >= ET) return;
    int s, d;
    if (i < NE) {
        if (is64) { s = e32[2 * i]; d = e32[2 * (NE + i)]; }
        else      { s = e32[i];     d = e32[NE + i]; }
    } else {
        s = d = i - NE;
    }
    int pos = atomicAdd(&g_cur[d], 1);
    g_col[pos] = s;
}

// ==================== w_prep: W1^T -> bf16 hi/lo, linear [n][k] ====================
__global__ void w_prep(const float* __restrict__ W) {
    int i = blockIdx.x * blockDim.x + threadIdx.x;
    if (i >= 128 * 32) return;
    int n = i >> 5, k4 = (i & 31) * 4;
    float v0 = W[(k4 + 0) * 128 + n];
    float v1 = W[(k4 + 1) * 128 + n];
    float v2 = W[(k4 + 2) * 128 + n];
    float v3 = W[(k4 + 3) * 128 + n];
    __nv_bfloat162 h01 = __floats2bfloat162_rn(v0, v1);
    __nv_bfloat162 h23 = __floats2bfloat162_rn(v2, v3);
    __nv_bfloat162 l01 = __floats2bfloat162_rn(v0 - __low2float(h01), v1 - __high2float(h01));
    __nv_bfloat162 l23 = __floats2bfloat162_rn(v2 - __low2float(h23), v3 - __high2float(h23));
    uint32_t* hi = (uint32_t*)g_wt_hi;
    uint32_t* lo = (uint32_t*)g_wt_lo;
    int w32 = (n * 128 + k4) >> 1;
    hi[w32] = *(uint32_t*)&h01; hi[w32 + 1] = *(uint32_t*)&h23;
    lo[w32] = *(uint32_t*)&l01; lo[w32 + 1] = *(uint32_t*)&l23;
}

// ==================== GEMM1 via mma.sync: 64 rows/CTA, 2 CTAs/SM ====================
// warp (slab = wid&3, half = wid>>2): rows slab*16..+15, cols half*64..+63 (8 n-tiles).
#define XSTR 136
#define SM_ATT 0
#define SM_ATD 512
#define SM_XHI 1024
#define SM_XLO (1024 + 17408)
#define SM_WHI (1024 + 34816)
#define SM_WLO (1024 + 69632)
#define G1_SMEM (1024 + 104448)

__global__ void __launch_bounds__(256, 2)
gemm1_tc(const float* __restrict__ x, const float* __restrict__ atts, const float* __restrict__ attd) {
    extern __shared__ char smem[];
    int t = threadIdx.x, lane = t & 31, wid = t >> 5;
    int row0 = blockIdx.x * 64;

    if (t < 128) {
        ((float*)(smem + SM_ATT))[t] = atts[t];
        ((float*)(smem + SM_ATD))[t] = attd[t];
    }

    // x tile (64 rows) -> bf16 hi/lo
    for (int i = t; i < 2048; i += 256) {
        int r = i >> 5, c4 = (i & 31) * 4;
        int row = row0 + r;
        float4 v = (row < NN) ? *(const float4*)&x[row * 128 + c4]
                              : make_float4(0.f, 0.f, 0.f, 0.f);
        __nv_bfloat162 h01 = __floats2bfloat162_rn(v.x, v.y);
        __nv_bfloat162 h23 = __floats2bfloat162_rn(v.z, v.w);
        __nv_bfloat162 l01 = __floats2bfloat162_rn(v.x - __low2float(h01), v.y - __high2float(h01));
        __nv_bfloat162 l23 = __floats2bfloat162_rn(v.z - __low2float(h23), v.w - __high2float(h23));
        int off = (r * XSTR + c4) * 2;
        *(uint32_t*)(smem + SM_XHI + off)     = *(uint32_t*)&h01;
        *(uint32_t*)(smem + SM_XHI + off + 4) = *(uint32_t*)&h23;
        *(uint32_t*)(smem + SM_XLO + off)     = *(uint32_t*)&l01;
        *(uint32_t*)(smem + SM_XLO + off + 4) = *(uint32_t*)&l23;
    }
    // W^T tiles: linear gmem -> strided smem
    for (int i = t; i < 2048; i += 256) {
        int n = i >> 4, k8 = (i & 15) * 8;
        int off = (n * XSTR + k8) * 2;
        *(uint4*)(smem + SM_WHI + off) = g_wt_hi[i];
        *(uint4*)(smem + SM_WLO + off) = g_wt_lo[i];
    }
    __syncthreads();

    int q = lane >> 2, c2 = (lane & 3) * 2;
    int slab = wid & 3, half = wid >> 2;
    int wrow = slab * 16;

    float acc[8][4];
#pragma unroll
    for (int j = 0; j < 8; j++)
#pragma unroll
        for (int u = 0; u < 4; u++) acc[j][u] = 0.f;

#pragma unroll
    for (int ks = 0; ks < 8; ks++) {
        int abase = ((wrow + q) * XSTR + ks * 16 + c2) * 2;
        uint32_t ah[4], al[4];
        ah[0] = *(uint32_t*)(smem + SM_XHI + abase);
        ah[1] = *(uint32_t*)(smem + SM_XHI + abase + 8 * XSTR * 2);
        ah[2] = *(uint32_t*)(smem + SM_XHI + abase + 16);
        ah[3] = *(uint32_t*)(smem + SM_XHI + abase + 8 * XSTR * 2 + 16);
        al[0] = *(uint32_t*)(smem + SM_XLO + abase);
        al[1] = *(uint32_t*)(smem + SM_XLO + abase + 8 * XSTR * 2);
        al[2] = *(uint32_t*)(smem + SM_XLO + abase + 16);
        al[3] = *(uint32_t*)(smem + SM_XLO + abase + 8 * XSTR * 2 + 16);
#pragma unroll
        for (int j = 0; j < 8; j++) {
            int nt = half * 8 + j;
            int bbase = ((nt * 8 + q) * XSTR + ks * 16 + c2) * 2;
            uint32_t bh[2], bl[2];
            bh[0] = *(uint32_t*)(smem + SM_WHI + bbase);
            bh[1] = *(uint32_t*)(smem + SM_WHI + bbase + 16);
            bl[0] = *(uint32_t*)(smem + SM_WLO + bbase);
            bl[1] = *(uint32_t*)(smem + SM_WLO + bbase + 16);
            mma16816(acc[j], ah, bh);
            mma16816(acc[j], ah, bl);
            mma16816(acc[j], al, bh);
        }
    }

    // epilogue: store h1, per-head attention dots (4 heads per warp), quad-reduce
    const float* satt = (const float*)(smem + SM_ATT);
    const float* satd = (const float*)(smem + SM_ATD);
    int rowA = row0 + wrow + q;
    int rowB = rowA + 8;
    float psA[4], pdA[4], psB[4], pdB[4];
#pragma unroll
    for (int h = 0; h < 4; h++) { psA[h] = pdA[h] = psB[h] = pdB[h] = 0.f; }

#pragma unroll
    for (int j = 0; j < 8; j++) {
        int nt = half * 8 + j;
        int col = nt * 8 + c2;
        int hl = j >> 1;
        float d0 = acc[j][0], d1 = acc[j][1], d2 = acc[j][2], d3 = acc[j][3];
        float t0 = satt[col], t1 = satt[col + 1];
        float u0 = satd[col], u1 = satd[col + 1];
        psA[hl] += d0 * t0 + d1 * t1; pdA[hl] += d0 * u0 + d1 * u1;
        psB[hl] += d2 * t0 + d3 * t1; pdB[hl] += d2 * u0 + d3 * u1;
        if (rowA < NN) *(float2*)&g_h1[rowA * 128 + col] = make_float2(d0, d1);
        if (rowB < NN) *(float2*)&g_h1[rowB * 128 + col] = make_float2(d2, d3);
    }
#pragma unroll
    for (int h = 0; h < 4; h++) {
        psA[h] += __shfl_xor_sync(0xffffffffu, psA[h], 1);
        psA[h] += __shfl_xor_sync(0xffffffffu, psA[h], 2);
        pdA[h] += __shfl_xor_sync(0xffffffffu, pdA[h], 1);
        pdA[h] += __shfl_xor_sync(0xffffffffu, pdA[h], 2);
        psB[h] += __shfl_xor_sync(0xffffffffu, psB[h], 1);
        psB[h] += __shfl_xor_sync(0xffffffffu, psB[h], 2);
        pdB[h] += __shfl_xor_sync(0xffffffffu, pdB[h], 1);
        pdB[h] += __shfl_xor_sync(0xffffffffu, pdB[h], 2);
    }
    int c = lane & 3;      // quad-lane c writes head half*4 + c
    int h = half * 4 + c;
    if (rowA < NN) { g_as1[rowA * 8 + h] = psA[c]; g_ad1[rowA * 8 + h] = pdA[c]; }
    if (rowB < NN) { g_as1[rowB * 8 + h] = psB[c]; g_ad1[rowB * 8 + h] = pdB[c]; }
}

// ==================== fused layer1: single-pass, bank-conflict-free staging ====================
__global__ void l1_gather(const float* __restrict__ b1) {
    __shared__ float sex[8][8][33];
    int w = (blockIdx.x * blockDim.x + threadIdx.x) >> 5;
    int wid = (threadIdx.x >> 5) & 7;
    int lane = threadIdx.x & 31;
    if (w >= NN) return;
    int beg = g_rp[w], end = g_rp[w + 1];

    float4 ad0 = *(const float4*)&g_ad1[w * 8];
    float4 ad1v = *(const float4*)&g_ad1[w * 8 + 4];

    int h = lane >> 2;
    float dn[8] = {};
    float4 acc = make_float4(0.f, 0.f, 0.f, 0.f);

    for (int base = beg; base < end; base += 32) {
        int idx = base + lane;
        int sc = (idx < end) ? g_col[idx] : 0;
        float msk = (idx < end) ? 1.f : 0.f;
        {
            float4 s0 = *(const float4*)&g_as1[sc * 8];
            float4 s1 = *(const float4*)&g_as1[sc * 8 + 4];
            float e0 = __expf(lrelu(s0.x + ad0.x)) * msk;
            float e1 = __expf(lrelu(s0.y + ad0.y)) * msk;
            float e2 = __expf(lrelu(s0.z + ad0.z)) * msk;
            float e3 = __expf(lrelu(s0.w + ad0.w)) * msk;
            float e4 = __expf(lrelu(s1.x + ad1v.x)) * msk;
            float e5 = __expf(lrelu(s1.y + ad1v.y)) * msk;
            float e6 = __expf(lrelu(s1.z + ad1v.z)) * msk;
            float e7 = __expf(lrelu(s1.w + ad1v.w)) * msk;
            sex[wid][0][lane] = e0; dn[0] += e0;
            sex[wid][1][lane] = e1; dn[1] += e1;
            sex[wid][2][lane] = e2; dn[2] += e2;
            sex[wid][3][lane] = e3; dn[3] += e3;
            sex[wid][4][lane] = e4; dn[4] += e4;
            sex[wid][5][lane] = e5; dn[5] += e5;
            sex[wid][6][lane] = e6; dn[6] += e6;
            sex[wid][7][lane] = e7; dn[7] += e7;
        }
        __syncwarp();
        int n = min(32, end - base);
#pragma unroll 4
        for (int j = 0; j < n; j++) {
            int s = __shfl_sync(0xffffffffu, sc, j);
            float a = sex[wid][h][j];
            float4 v = *(const float4*)&g_h1[s * 128 + lane * 4];
            acc.x += a * v.x; acc.y += a * v.y;
            acc.z += a * v.z; acc.w += a * v.w;
        }
        __syncwarp();
    }

#pragma unroll
    for (int hh = 0; hh < 8; hh++)
        for (int off = 16; off; off >>= 1)
            dn[hh] += __shfl_xor_sync(0xffffffffu, dn[hh], off);
    float rdn = 1.f / (dn[h] + 1e-16f);

    float4 bb = *(const float4*)&b1[lane * 4];
    acc.x = acc.x * rdn + bb.x;
    acc.y = acc.y * rdn + bb.y;
    acc.z = acc.z * rdn + bb.z;
    acc.w = acc.w * rdn + bb.w;
    acc.x = acc.x > 0.f ? acc.x : expm1f(acc.x);
    acc.y = acc.y > 0.f ? acc.y : expm1f(acc.y);
    acc.z = acc.z > 0.f ? acc.z : expm1f(acc.z);
    acc.w = acc.w > 0.f ? acc.w : expm1f(acc.w);
    *(float4*)&g_o1[w * 128 + lane * 4] = acc;
}

// ==================== GEMM2 (128->40, LDS.128 f32x2) with fused a2 dots ====================
__global__ void gemm2_kernel(const float* __restrict__ W,
                             const float* __restrict__ atts, const float* __restrict__ attd) {
    extern __shared__ float sm[];
    float* xs = sm + 5120;
    float* sa = sm + 5120 + 8448;
    float* sd = sa + 64;
    int t = threadIdx.x;
    int ct = t % 10, rt = t / 10;
    int row0 = blockIdx.x * 64;

    for (int i = t; i < 5120; i += 160) {
        int k = i / 40, c = i % 40;
        sm[(k >> 2) * 160 + (c & 3) * 40 + (c >> 2) * 4 + (k & 3)] = W[i];
    }
    for (int i = t; i < 2048; i += 160) {
        int r = i >> 5, k4 = (i & 31) * 4;
        int row = row0 + r;
        float4 v = (row < NN) ? *(const float4*)&g_o1[row * 128 + k4]
                              : make_float4(0.f, 0.f, 0.f, 0.f);
        *(float4*)&xs[r * 132 + k4] = v;
    }
    if (t < 64) { sa[t] = 0.f; sd[t] = 0.f; }
    __syncthreads();

    u64 acc2[4][4];
#pragma unroll
    for (int i = 0; i < 4; i++)
#pragma unroll
        for (int c = 0; c < 4; c++) acc2[i][c] = 0ull;

#pragma unroll 2
    for (int kpp = 0; kpp < 32; kpp++) {
        const float* wb = sm + kpp * 160 + 4 * ct;
        ulonglong2 w0 = *(const ulonglong2*)(wb);
        ulonglong2 w1 = *(const ulonglong2*)(wb + 40);
        ulonglong2 w2 = *(const ulonglong2*)(wb + 80);
        ulonglong2 w3 = *(const ulonglong2*)(wb + 120);
#pragma unroll
        for (int i = 0; i < 4; i++) {
            ulonglong2 xp = *(const ulonglong2*)&xs[(rt * 4 + i) * 132 + 4 * kpp];
            ffma2(acc2[i][0], xp.x, w0.x); ffma2(acc2[i][0], xp.y, w0.y);
            ffma2(acc2[i][1], xp.x, w1.x); ffma2(acc2[i][1], xp.y, w1.y);
            ffma2(acc2[i][2], xp.x, w2.x); ffma2(acc2[i][2], xp.y, w2.y);
            ffma2(acc2[i][3], xp.x, w3.x); ffma2(acc2[i][3], xp.y, w3.y);
        }
    }

    float4 avs = *(const float4*)&atts[4 * ct];
    float4 avd = *(const float4*)&attd[4 * ct];
#pragma unroll
    for (int i = 0; i < 4; i++) {
        float a[4];
#pragma unroll
        for (int c = 0; c < 4; c++) {
            float lo, hi; upk2(lo, hi, acc2[i][c]);
            a[c] = lo + hi;
        }
        int row = row0 + rt * 4 + i;
        if (row < NN)
            *(float4*)&g_z[row * 40 + 4 * ct] = make_float4(a[0], a[1], a[2], a[3]);
        float ps = a[0] * avs.x + a[1] * avs.y + a[2] * avs.z + a[3] * avs.w;
        float pd = a[0] * avd.x + a[1] * avd.y + a[2] * avd.z + a[3] * avd.w;
        atomicAdd(&sa[rt * 4 + i], ps);
        atomicAdd(&sd[rt * 4 + i], pd);
    }
    __syncthreads();
    if (t < 64) {
        int row = row0 + t;
        if (row < NN) { g_as2[row] = sa[t]; g_ad2[row] = sd[t]; }
    }
}

// ==================== fused layer2: single-pass + bias + log_softmax ====================
__global__ void l2_gather(float* __restrict__ out, const float* __restrict__ b2) {
    int w = (blockIdx.x * blockDim.x + threadIdx.x) >> 5;
    int lane = threadIdx.x & 31;
    if (w >= NN) return;
    int beg = g_rp[w], end = g_rp[w + 1];
    float adw = g_ad2[w];

    float dn = 0.f;
    float a1 = 0.f, a2 = 0.f;
    for (int base = beg; base < end; base += 32) {
        int idx = base + lane;
        int sc = (idx < end) ? g_col[idx] : 0;
        float ex = (idx < end) ? __expf(lrelu(g_as2[sc] + adw)) : 0.f;
        dn += ex;
        int n = min(32, end - base);
#pragma unroll 4
        for (int j = 0; j < n; j++) {
            float al = __shfl_sync(0xffffffffu, ex, j);
            int s = __shfl_sync(0xffffffffu, sc, j);
            a1 += al * g_z[s * 40 + lane];
            if (lane < 8) a2 += al * g_z[s * 40 + 32 + lane];
        }
    }
    for (int off = 16; off; off >>= 1)
        dn += __shfl_xor_sync(0xffffffffu, dn, off);
    float rdn = 1.f / (dn + 1e-16f);

    float v1 = a1 * rdn + b2[lane];
    float v2 = (lane < 8) ? a2 * rdn + b2[32 + lane] : -1e30f;
    float m = fmaxf(v1, v2);
    for (int o = 16; o; o >>= 1) m = fmaxf(m, __shfl_xor_sync(0xffffffffu, m, o));
    float s = expf(v1 - m) + ((lane < 8) ? expf(v2 - m) : 0.f);
    for (int o = 16; o; o >>= 1) s += __shfl_xor_sync(0xffffffffu, s, o);
    float ls = m + logf(s);
    out[w * 40 + lane] = v1 - ls;
    if (lane < 8) out[w * 40 + 32 + lane] = v2 - ls;
}

// ==================== launch ====================
extern "C" void kernel_launch(void* const* d_in, const int* in_sizes, int n_in,
                              void* d_out, int out_size) {
    const float* x   = (const float*)d_in[0];
    const int*   ei  = (const int*)d_in[1];
    const float* W1  = (const float*)d_in[2];
    const float* as1 = (const float*)d_in[3];
    const float* ad1 = (const float*)d_in[4];
    const float* b1  = (const float*)d_in[5];
    const float* W2  = (const float*)d_in[6];
    const float* as2 = (const float*)d_in[7];
    const float* ad2 = (const float*)d_in[8];
    const float* b2  = (const float*)d_in[9];
    float* out = (float*)d_out;

    static cudaStream_t sB = nullptr;
    static cudaEvent_t evF = nullptr, evJ = nullptr;
    if (!sB) {
        cudaStreamCreateWithFlags(&sB, cudaStreamNonBlocking);
        cudaEventCreateWithFlags(&evF, cudaEventDisableTiming);
        cudaEventCreateWithFlags(&evJ, cudaEventDisableTiming);
    }

    const int SM2 = (5120 + 64 * 132 + 128) * 4;
    cudaFuncSetAttribute(gemm1_tc, cudaFuncAttributeMaxDynamicSharedMemorySize, G1_SMEM);
    cudaFuncSetAttribute(gemm2_kernel, cudaFuncAttributeMaxDynamicSharedMemorySize, SM2);

    // fork: CSR build on side stream; W-prep + tensor-core gemm1 on main stream.
    cudaEventRecord(evF, 0);
    cudaStreamWaitEvent(sB, evF, 0);

    w_prep<<<16, 256>>>(W1);                                  // 0 (main)
    hist_kernel<<<(ET + 255) / 256, 256, 0, sB>>>(ei);        // 1
    scan1<<<NB, 1024, 0, sB>>>();                             // 2
    gemm1_tc<<<(NN + 63) / 64, 256, G1_SMEM>>>(x, as1, ad1);  // 3 <- profiled
    scan2<<<1, 128, 0, sB>>>();                               // 4
    scan3<<<(NN + 255) / 256, 256, 0, sB>>>();                // 5
    scatter<<<(ET + 255) / 256, 256, 0, sB>>>(ei);            // 6
    cudaEventRecord(evJ, sB);

    cudaStreamWaitEvent(0, evJ, 0);

    l1_gather<<<(NN * 32 + 255) / 256, 256>>>(b1);
    gemm2_kernel<<<(NN + 63) / 64, 160, SM2>>>(W2, as2, ad2);
    l2_gather<<<(NN * 32 + 255) / 256, 256>>>(out, b2);
}

// round 14
// speedup vs baseline: 1.3006x; 1.0777x over previous
#include <cuda_runtime.h>
#include <cuda_bf16.h>
#include <cstdint>

#define NN 100000
#define NE 1600000
#define ET (NE + NN)
#define NB 98   // ceil(NN/1024) scan blocks

typedef unsigned long long u64;

// -------- scratch (device globals: no allocations allowed) --------
__device__ int   g_col[ET];
__device__ int   g_deg[NN];
__device__ int   g_scan[NN];
__device__ int   g_bsum[NB];
__device__ int   g_boff[NB];
__device__ int   g_rp[NN + 1];
__device__ int   g_cur[NN];
__device__ uint4 g_wt_hi[2048];   // W1^T bf16 hi, linear [n][k] (128x128)
__device__ uint4 g_wt_lo[2048];   // W1^T bf16 lo
__device__ float g_h1[NN * 128];
__device__ float g_as1[NN * 8];
__device__ float g_ad1[NN * 8];
__device__ float g_o1[NN * 128];
__device__ float g_z[NN * 40];
__device__ float g_as2[NN];
__device__ float g_ad2[NN];

__device__ __forceinline__ float lrelu(float v) { return v > 0.f ? v : 0.2f * v; }

__device__ __forceinline__ void ffma2(u64& d, u64 a, u64 b) {
    asm("fma.rn.f32x2 %0, %1, %2, %0;" : "+l"(d) : "l"(a), "l"(b));
}
__device__ __forceinline__ void upk2(float& lo, float& hi, u64 v) {
    asm("mov.b64 {%0, %1}, %2;" : "=f"(lo), "=f"(hi) : "l"(v));
}
__device__ __forceinline__ int detect64(const int* e32) {
    int z = 0;
#pragma unroll
    for (int j = 1; j <= 16; j++) z |= e32[2 * j + 1];
    return (z == 0) ? 1 : 0;
}

// mma.sync m16n8k16 row.col f32.bf16.bf16.f32 (baseline PTX, works on sm_103)
__device__ __forceinline__ void mma16816(float* d, const uint32_t* a, const uint32_t* b) {
    asm volatile(
        "mma.sync.aligned.m16n8k16.row.col.f32.bf16.bf16.f32 "
        "{%0,%1,%2,%3}, {%4,%5,%6,%7}, {%8,%9}, {%0,%1,%2,%3};"
        : "+f"(d[0]), "+f"(d[1]), "+f"(d[2]), "+f"(d[3])
        : "r"(a[0]), "r"(a[1]), "r"(a[2]), "r"(a[3]), "r"(b[0]), "r"(b[1]));
}

// ==================== CSR build ====================
__global__ void hist_kernel(const int* __restrict__ e32) {
    __shared__ int is64;
    if (threadIdx.x == 0) is64 = detect64(e32);
    __syncthreads();
    int i = blockIdx.x * blockDim.x + threadIdx.x;
    if (i >= ET) return;
    int d;
    if (i < NE) d = is64 ? e32[2 * (NE + i)] : e32[NE + i];
    else        d = i - NE;
    atomicAdd(&g_deg[d], 1);
}

__global__ void scan1() {
    __shared__ int sm[1024];
    int i = blockIdx.x * 1024 + threadIdx.x;
    int v = (i < NN) ? g_deg[i] : 0;
    sm[threadIdx.x] = v;
    __syncthreads();
    for (int off = 1; off < 1024; off <<= 1) {
        int t = (threadIdx.x >= off) ? sm[threadIdx.x - off] : 0;
        __syncthreads();
        sm[threadIdx.x] += t;
        __syncthreads();
    }
    if (i < NN) g_scan[i] = sm[threadIdx.x];
    if (threadIdx.x == 1023) g_bsum[blockIdx.x] = sm[1023];
}

__global__ void scan2() {
    __shared__ int sm[128];
    int t = threadIdx.x;
    int v = (t < NB) ? g_bsum[t] : 0;
    sm[t] = v;
    __syncthreads();
    for (int off = 1; off < 128; off <<= 1) {
        int a = (t >= off) ? sm[t - off] : 0;
        __syncthreads();
        sm[t] += a;
        __syncthreads();
    }
    if (t < NB) g_boff[t] = sm[t] - v;
}

__global__ void scan3() {
    int i = blockIdx.x * blockDim.x + threadIdx.x;
    if (i >= NN) return;
    int incl = g_scan[i] + g_boff[i >> 10];
    g_rp[i + 1] = incl;
    g_cur[i] = incl - g_deg[i];
    if (i == 0) g_rp[0] = 0;
}

__global__ void scatter(const int* __restrict__ e32) {
    __shared__ int is64;
    if (threadIdx.x == 0) is64 = detect64(e32);
    __syncthreads();
    int i = blockIdx.x * blockDim.x + threadIdx.x;
    if (i < NN) g_deg[i] = 0;
    if (i >= ET) return;
    int s, d;
    if (i < NE) {
        if (is64) { s = e32[2 * i]; d = e32[2 * (NE + i)]; }
        else      { s = e32[i];     d = e32[NE + i]; }
    } else {
        s = d = i - NE;
    }
    int pos = atomicAdd(&g_cur[d], 1);
    g_col[pos] = s;
}

// ==================== w_prep: W1^T -> bf16 hi/lo, linear [n][k] ====================
__global__ void w_prep(const float* __restrict__ W) {
    int i = blockIdx.x * blockDim.x + threadIdx.x;
    if (i >= 128 * 32) return;
    int n = i >> 5, k4 = (i & 31) * 4;
    float v0 = W[(k4 + 0) * 128 + n];
    float v1 = W[(k4 + 1) * 128 + n];
    float v2 = W[(k4 + 2) * 128 + n];
    float v3 = W[(k4 + 3) * 128 + n];
    __nv_bfloat162 h01 = __floats2bfloat162_rn(v0, v1);
    __nv_bfloat162 h23 = __floats2bfloat162_rn(v2, v3);
    __nv_bfloat162 l01 = __floats2bfloat162_rn(v0 - __low2float(h01), v1 - __high2float(h01));
    __nv_bfloat162 l23 = __floats2bfloat162_rn(v2 - __low2float(h23), v3 - __high2float(h23));
    uint32_t* hi = (uint32_t*)g_wt_hi;
    uint32_t* lo = (uint32_t*)g_wt_lo;
    int w32 = (n * 128 + k4) >> 1;
    hi[w32] = *(uint32_t*)&h01; hi[w32 + 1] = *(uint32_t*)&h23;
    lo[w32] = *(uint32_t*)&l01; lo[w32 + 1] = *(uint32_t*)&l23;
}

// ==================== GEMM1 via mma.sync: 64 rows/CTA, 2 CTAs/SM ====================
#define XSTR 136
#define SM_ATT 0
#define SM_ATD 512
#define SM_XHI 1024
#define SM_XLO (1024 + 17408)
#define SM_WHI (1024 + 34816)
#define SM_WLO (1024 + 69632)
#define G1_SMEM (1024 + 104448)

__global__ void __launch_bounds__(256, 2)
gemm1_tc(const float* __restrict__ x, const float* __restrict__ atts, const float* __restrict__ attd) {
    extern __shared__ char smem[];
    int t = threadIdx.x, lane = t & 31, wid = t >> 5;
    int row0 = blockIdx.x * 64;

    if (t < 128) {
        ((float*)(smem + SM_ATT))[t] = atts[t];
        ((float*)(smem + SM_ATD))[t] = attd[t];
    }

    for (int i = t; i < 2048; i += 256) {
        int r = i >> 5, c4 = (i & 31) * 4;
        int row = row0 + r;
        float4 v = (row < NN) ? *(const float4*)&x[row * 128 + c4]
                              : make_float4(0.f, 0.f, 0.f, 0.f);
        __nv_bfloat162 h01 = __floats2bfloat162_rn(v.x, v.y);
        __nv_bfloat162 h23 = __floats2bfloat162_rn(v.z, v.w);
        __nv_bfloat162 l01 = __floats2bfloat162_rn(v.x - __low2float(h01), v.y - __high2float(h01));
        __nv_bfloat162 l23 = __floats2bfloat162_rn(v.z - __low2float(h23), v.w - __high2float(h23));
        int off = (r * XSTR + c4) * 2;
        *(uint32_t*)(smem + SM_XHI + off)     = *(uint32_t*)&h01;
        *(uint32_t*)(smem + SM_XHI + off + 4) = *(uint32_t*)&h23;
        *(uint32_t*)(smem + SM_XLO + off)     = *(uint32_t*)&l01;
        *(uint32_t*)(smem + SM_XLO + off + 4) = *(uint32_t*)&l23;
    }
    for (int i = t; i < 2048; i += 256) {
        int n = i >> 4, k8 = (i & 15) * 8;
        int off = (n * XSTR + k8) * 2;
        *(uint4*)(smem + SM_WHI + off) = g_wt_hi[i];
        *(uint4*)(smem + SM_WLO + off) = g_wt_lo[i];
    }
    __syncthreads();

    int q = lane >> 2, c2 = (lane & 3) * 2;
    int slab = wid & 3, half = wid >> 2;
    int wrow = slab * 16;

    float acc[8][4];
#pragma unroll
    for (int j = 0; j < 8; j++)
#pragma unroll
        for (int u = 0; u < 4; u++) acc[j][u] = 0.f;

#pragma unroll
    for (int ks = 0; ks < 8; ks++) {
        int abase = ((wrow + q) * XSTR + ks * 16 + c2) * 2;
        uint32_t ah[4], al[4];
        ah[0] = *(uint32_t*)(smem + SM_XHI + abase);
        ah[1] = *(uint32_t*)(smem + SM_XHI + abase + 8 * XSTR * 2);
        ah[2] = *(uint32_t*)(smem + SM_XHI + abase + 16);
        ah[3] = *(uint32_t*)(smem + SM_XHI + abase + 8 * XSTR * 2 + 16);
        al[0] = *(uint32_t*)(smem + SM_XLO + abase);
        al[1] = *(uint32_t*)(smem + SM_XLO + abase + 8 * XSTR * 2);
        al[2] = *(uint32_t*)(smem + SM_XLO + abase + 16);
        al[3] = *(uint32_t*)(smem + SM_XLO + abase + 8 * XSTR * 2 + 16);
#pragma unroll
        for (int j = 0; j < 8; j++) {
            int nt = half * 8 + j;
            int bbase = ((nt * 8 + q) * XSTR + ks * 16 + c2) * 2;
            uint32_t bh[2], bl[2];
            bh[0] = *(uint32_t*)(smem + SM_WHI + bbase);
            bh[1] = *(uint32_t*)(smem + SM_WHI + bbase + 16);
            bl[0] = *(uint32_t*)(smem + SM_WLO + bbase);
            bl[1] = *(uint32_t*)(smem + SM_WLO + bbase + 16);
            mma16816(acc[j], ah, bh);
            mma16816(acc[j], ah, bl);
            mma16816(acc[j], al, bh);
        }
    }

    const float* satt = (const float*)(smem + SM_ATT);
    const float* satd = (const float*)(smem + SM_ATD);
    int rowA = row0 + wrow + q;
    int rowB = rowA + 8;
    float psA[4], pdA[4], psB[4], pdB[4];
#pragma unroll
    for (int h = 0; h < 4; h++) { psA[h] = pdA[h] = psB[h] = pdB[h] = 0.f; }

#pragma unroll
    for (int j = 0; j < 8; j++) {
        int nt = half * 8 + j;
        int col = nt * 8 + c2;
        int hl = j >> 1;
        float d0 = acc[j][0], d1 = acc[j][1], d2 = acc[j][2], d3 = acc[j][3];
        float t0 = satt[col], t1 = satt[col + 1];
        float u0 = satd[col], u1 = satd[col + 1];
        psA[hl] += d0 * t0 + d1 * t1; pdA[hl] += d0 * u0 + d1 * u1;
        psB[hl] += d2 * t0 + d3 * t1; pdB[hl] += d2 * u0 + d3 * u1;
        if (rowA < NN) *(float2*)&g_h1[rowA * 128 + col] = make_float2(d0, d1);
        if (rowB < NN) *(float2*)&g_h1[rowB * 128 + col] = make_float2(d2, d3);
    }
#pragma unroll
    for (int h = 0; h < 4; h++) {
        psA[h] += __shfl_xor_sync(0xffffffffu, psA[h], 1);
        psA[h] += __shfl_xor_sync(0xffffffffu, psA[h], 2);
        pdA[h] += __shfl_xor_sync(0xffffffffu, pdA[h], 1);
        pdA[h] += __shfl_xor_sync(0xffffffffu, pdA[h], 2);
        psB[h] += __shfl_xor_sync(0xffffffffu, psB[h], 1);
        psB[h] += __shfl_xor_sync(0xffffffffu, psB[h], 2);
        pdB[h] += __shfl_xor_sync(0xffffffffu, pdB[h], 1);
        pdB[h] += __shfl_xor_sync(0xffffffffu, pdB[h], 2);
    }
    int c = lane & 3;
    int h = half * 4 + c;
    if (rowA < NN) { g_as1[rowA * 8 + h] = psA[c]; g_ad1[rowA * 8 + h] = pdA[c]; }
    if (rowB < NN) { g_as1[rowB * 8 + h] = psB[c]; g_ad1[rowB * 8 + h] = pdB[c]; }
}

// ==================== fused layer1: single-pass, MLP-2 gather ====================
__global__ void l1_gather(const float* __restrict__ b1) {
    __shared__ float sex[8][8][33];
    int w = (blockIdx.x * blockDim.x + threadIdx.x) >> 5;
    int wid = (threadIdx.x >> 5) & 7;
    int lane = threadIdx.x & 31;
    if (w >= NN) return;
    int beg = g_rp[w], end = g_rp[w + 1];

    float4 ad0 = *(const float4*)&g_ad1[w * 8];
    float4 ad1v = *(const float4*)&g_ad1[w * 8 + 4];

    int h = lane >> 2;
    float dn[8] = {};
    float4 acc = make_float4(0.f, 0.f, 0.f, 0.f);

    for (int base = beg; base < end; base += 32) {
        int idx = base + lane;
        int sc = (idx < end) ? g_col[idx] : 0;
        float msk = (idx < end) ? 1.f : 0.f;
        {
            float4 s0 = *(const float4*)&g_as1[sc * 8];
            float4 s1 = *(const float4*)&g_as1[sc * 8 + 4];
            float e0 = __expf(lrelu(s0.x + ad0.x)) * msk;
            float e1 = __expf(lrelu(s0.y + ad0.y)) * msk;
            float e2 = __expf(lrelu(s0.z + ad0.z)) * msk;
            float e3 = __expf(lrelu(s0.w + ad0.w)) * msk;
            float e4 = __expf(lrelu(s1.x + ad1v.x)) * msk;
            float e5 = __expf(lrelu(s1.y + ad1v.y)) * msk;
            float e6 = __expf(lrelu(s1.z + ad1v.z)) * msk;
            float e7 = __expf(lrelu(s1.w + ad1v.w)) * msk;
            sex[wid][0][lane] = e0; dn[0] += e0;
            sex[wid][1][lane] = e1; dn[1] += e1;
            sex[wid][2][lane] = e2; dn[2] += e2;
            sex[wid][3][lane] = e3; dn[3] += e3;
            sex[wid][4][lane] = e4; dn[4] += e4;
            sex[wid][5][lane] = e5; dn[5] += e5;
            sex[wid][6][lane] = e6; dn[6] += e6;
            sex[wid][7][lane] = e7; dn[7] += e7;
        }
        __syncwarp();
        int n = min(32, end - base);
        int j = 0;
        for (; j + 2 <= n; j += 2) {
            int s0 = __shfl_sync(0xffffffffu, sc, j);
            int s1 = __shfl_sync(0xffffffffu, sc, j + 1);
            float a0 = sex[wid][h][j];
            float a1 = sex[wid][h][j + 1];
            float4 v0 = *(const float4*)&g_h1[s0 * 128 + lane * 4];
            float4 v1 = *(const float4*)&g_h1[s1 * 128 + lane * 4];
            acc.x += a0 * v0.x; acc.y += a0 * v0.y;
            acc.z += a0 * v0.z; acc.w += a0 * v0.w;
            acc.x += a1 * v1.x; acc.y += a1 * v1.y;
            acc.z += a1 * v1.z; acc.w += a1 * v1.w;
        }
        if (j < n) {
            int s0 = __shfl_sync(0xffffffffu, sc, j);
            float a0 = sex[wid][h][j];
            float4 v0 = *(const float4*)&g_h1[s0 * 128 + lane * 4];
            acc.x += a0 * v0.x; acc.y += a0 * v0.y;
            acc.z += a0 * v0.z; acc.w += a0 * v0.w;
        }
        __syncwarp();
    }

#pragma unroll
    for (int hh = 0; hh < 8; hh++)
        for (int off = 16; off; off >>= 1)
            dn[hh] += __shfl_xor_sync(0xffffffffu, dn[hh], off);
    float rdn = 1.f / (dn[h] + 1e-16f);

    float4 bb = *(const float4*)&b1[lane * 4];
    acc.x = acc.x * rdn + bb.x;
    acc.y = acc.y * rdn + bb.y;
    acc.z = acc.z * rdn + bb.z;
    acc.w = acc.w * rdn + bb.w;
    acc.x = acc.x > 0.f ? acc.x : expm1f(acc.x);
    acc.y = acc.y > 0.f ? acc.y : expm1f(acc.y);
    acc.z = acc.z > 0.f ? acc.z : expm1f(acc.z);
    acc.w = acc.w > 0.f ? acc.w : expm1f(acc.w);
    *(float4*)&g_o1[w * 128 + lane * 4] = acc;
}

// ==================== GEMM2 (128->40, LDS.128 f32x2) with fused a2 dots ====================
__global__ void gemm2_kernel(const float* __restrict__ W,
                             const float* __restrict__ atts, const float* __restrict__ attd) {
    extern __shared__ float sm[];
    float* xs = sm + 5120;
    float* sa = sm + 5120 + 8448;
    float* sd = sa + 64;
    int t = threadIdx.x;
    int ct = t % 10, rt = t / 10;
    int row0 = blockIdx.x * 64;

    for (int i = t; i < 5120; i += 160) {
        int k = i / 40, c = i % 40;
        sm[(k >> 2) * 160 + (c & 3) * 40 + (c >> 2) * 4 + (k & 3)] = W[i];
    }
    for (int i = t; i < 2048; i += 160) {
        int r = i >> 5, k4 = (i & 31) * 4;
        int row = row0 + r;
        float4 v = (row < NN) ? *(const float4*)&g_o1[row * 128 + k4]
                              : make_float4(0.f, 0.f, 0.f, 0.f);
        *(float4*)&xs[r * 132 + k4] = v;
    }
    if (t < 64) { sa[t] = 0.f; sd[t] = 0.f; }
    __syncthreads();

    u64 acc2[4][4];
#pragma unroll
    for (int i = 0; i < 4; i++)
#pragma unroll
        for (int c = 0; c < 4; c++) acc2[i][c] = 0ull;

#pragma unroll 2
    for (int kpp = 0; kpp < 32; kpp++) {
        const float* wb = sm + kpp * 160 + 4 * ct;
        ulonglong2 w0 = *(const ulonglong2*)(wb);
        ulonglong2 w1 = *(const ulonglong2*)(wb + 40);
        ulonglong2 w2 = *(const ulonglong2*)(wb + 80);
        ulonglong2 w3 = *(const ulonglong2*)(wb + 120);
#pragma unroll
        for (int i = 0; i < 4; i++) {
            ulonglong2 xp = *(const ulonglong2*)&xs[(rt * 4 + i) * 132 + 4 * kpp];
            ffma2(acc2[i][0], xp.x, w0.x); ffma2(acc2[i][0], xp.y, w0.y);
            ffma2(acc2[i][1], xp.x, w1.x); ffma2(acc2[i][1], xp.y, w1.y);
            ffma2(acc2[i][2], xp.x, w2.x); ffma2(acc2[i][2], xp.y, w2.y);
            ffma2(acc2[i][3], xp.x, w3.x); ffma2(acc2[i][3], xp.y, w3.y);
        }
    }

    float4 avs = *(const float4*)&atts[4 * ct];
    float4 avd = *(const float4*)&attd[4 * ct];
#pragma unroll
    for (int i = 0; i < 4; i++) {
        float a[4];
#pragma unroll
        for (int c = 0; c < 4; c++) {
            float lo, hi; upk2(lo, hi, acc2[i][c]);
            a[c] = lo + hi;
        }
        int row = row0 + rt * 4 + i;
        if (row < NN)
            *(float4*)&g_z[row * 40 + 4 * ct] = make_float4(a[0], a[1], a[2], a[3]);
        float ps = a[0] * avs.x + a[1] * avs.y + a[2] * avs.z + a[3] * avs.w;
        float pd = a[0] * avd.x + a[1] * avd.y + a[2] * avd.z + a[3] * avd.w;
        atomicAdd(&sa[rt * 4 + i], ps);
        atomicAdd(&sd[rt * 4 + i], pd);
    }
    __syncthreads();
    if (t < 64) {
        int row = row0 + t;
        if (row < NN) { g_as2[row] = sa[t]; g_ad2[row] = sd[t]; }
    }
}

// ==================== fused layer2: single-pass, MLP-2 + bias + log_softmax ====================
__global__ void l2_gather(float* __restrict__ out, const float* __restrict__ b2) {
    int w = (blockIdx.x * blockDim.x + threadIdx.x) >> 5;
    int lane = threadIdx.x & 31;
    if (w >= NN) return;
    int beg = g_rp[w], end = g_rp[w + 1];
    float adw = g_ad2[w];

    float dn = 0.f;
    float a1 = 0.f, a2 = 0.f;
    for (int base = beg; base < end; base += 32) {
        int idx = base + lane;
        int sc = (idx < end) ? g_col[idx] : 0;
        float ex = (idx < end) ? __expf(lrelu(g_as2[sc] + adw)) : 0.f;
        dn += ex;
        int n = min(32, end - base);
        int j = 0;
        for (; j + 2 <= n; j += 2) {
            float al0 = __shfl_sync(0xffffffffu, ex, j);
            float al1 = __shfl_sync(0xffffffffu, ex, j + 1);
            int s0 = __shfl_sync(0xffffffffu, sc, j);
            int s1 = __shfl_sync(0xffffffffu, sc, j + 1);
            float z00 = g_z[s0 * 40 + lane];
            float z10 = g_z[s1 * 40 + lane];
            float z01 = (lane < 8) ? g_z[s0 * 40 + 32 + lane] : 0.f;
            float z11 = (lane < 8) ? g_z[s1 * 40 + 32 + lane] : 0.f;
            a1 += al0 * z00 + al1 * z10;
            a2 += al0 * z01 + al1 * z11;
        }
        if (j < n) {
            float al0 = __shfl_sync(0xffffffffu, ex, j);
            int s0 = __shfl_sync(0xffffffffu, sc, j);
            a1 += al0 * g_z[s0 * 40 + lane];
            if (lane < 8) a2 += al0 * g_z[s0 * 40 + 32 + lane];
        }
    }
    for (int off = 16; off; off >>= 1)
        dn += __shfl_xor_sync(0xffffffffu, dn, off);
    float rdn = 1.f / (dn + 1e-16f);

    float v1 = a1 * rdn + b2[lane];
    float v2 = (lane < 8) ? a2 * rdn + b2[32 + lane] : -1e30f;
    float m = fmaxf(v1, v2);
    for (int o = 16; o; o >>= 1) m = fmaxf(m, __shfl_xor_sync(0xffffffffu, m, o));
    float s = expf(v1 - m) + ((lane < 8) ? expf(v2 - m) : 0.f);
    for (int o = 16; o; o >>= 1) s += __shfl_xor_sync(0xffffffffu, s, o);
    float ls = m + logf(s);
    out[w * 40 + lane] = v1 - ls;
    if (lane < 8) out[w * 40 + 32 + lane] = v2 - ls;
}

// ==================== launch ====================
extern "C" void kernel_launch(void* const* d_in, const int* in_sizes, int n_in,
                              void* d_out, int out_size) {
    const float* x   = (const float*)d_in[0];
    const int*   ei  = (const int*)d_in[1];
    const float* W1  = (const float*)d_in[2];
    const float* as1 = (const float*)d_in[3];
    const float* ad1 = (const float*)d_in[4];
    const float* b1  = (const float*)d_in[5];
    const float* W2  = (const float*)d_in[6];
    const float* as2 = (const float*)d_in[7];
    const float* ad2 = (const float*)d_in[8];
    const float* b2  = (const float*)d_in[9];
    float* out = (float*)d_out;

    static cudaStream_t sB = nullptr;
    static cudaEvent_t evF = nullptr, evJ = nullptr;
    if (!sB) {
        cudaStreamCreateWithFlags(&sB, cudaStreamNonBlocking);
        cudaEventCreateWithFlags(&evF, cudaEventDisableTiming);
        cudaEventCreateWithFlags(&evJ, cudaEventDisableTiming);
    }

    const int SM2 = (5120 + 64 * 132 + 128) * 4;
    cudaFuncSetAttribute(gemm1_tc, cudaFuncAttributeMaxDynamicSharedMemorySize, G1_SMEM);
    cudaFuncSetAttribute(gemm2_kernel, cudaFuncAttributeMaxDynamicSharedMemorySize, SM2);

    // fork: CSR build on side stream; W-prep + tensor-core gemm1 on main stream.
    cudaEventRecord(evF, 0);
    cudaStreamWaitEvent(sB, evF, 0);

    w_prep<<<16, 256>>>(W1);                                  // 0 (main)
    hist_kernel<<<(ET + 255) / 256, 256, 0, sB>>>(ei);        // 1
    scan1<<<NB, 1024, 0, sB>>>();                             // 2
    gemm1_tc<<<(NN + 63) / 64, 256, G1_SMEM>>>(x, as1, ad1);  // 3 <- profiled
    scan2<<<1, 128, 0, sB>>>();                               // 4
    scan3<<<(NN + 255) / 256, 256, 0, sB>>>();                // 5
    scatter<<<(ET + 255) / 256, 256, 0, sB>>>(ei);            // 6
    cudaEventRecord(evJ, sB);

    cudaStreamWaitEvent(0, evJ, 0);

    l1_gather<<<(NN * 32 + 255) / 256, 256>>>(b1);
    gemm2_kernel<<<(NN + 63) / 64, 160, SM2>>>(W2, as2, ad2);
    l2_gather<<<(NN * 32 + 255) / 256, 256>>>(out, b2);
}

// round 15
// speedup vs baseline: 1.3438x; 1.0332x over previous
#include <cuda_runtime.h>
#include <cuda_bf16.h>
#include <cstdint>

#define NN 100000
#define NE 1600000
#define ET (NE + NN)
#define NB 98   // ceil(NN/1024) scan blocks

typedef unsigned long long u64;

// -------- scratch (device globals: no allocations allowed) --------
__device__ int   g_col[ET];
__device__ int   g_deg[NN];
__device__ int   g_scan[NN];
__device__ int   g_bsum[NB];
__device__ int   g_boff[NB];
__device__ int   g_rp[NN + 1];
__device__ int   g_cur[NN];
__device__ uint4 g_wt_hi[2048];   // W1^T bf16 hi, linear [n][k] (128x128)
__device__ uint4 g_wt_lo[2048];   // W1^T bf16 lo
__device__ float g_h1[NN * 128];
__device__ float g_as1[NN * 8];
__device__ float g_ad1[NN * 8];
__device__ float g_o1[NN * 128];
__device__ float g_z[NN * 40];
__device__ float g_as2[NN];
__device__ float g_ad2[NN];

__device__ __forceinline__ float lrelu(float v) { return v > 0.f ? v : 0.2f * v; }

__device__ __forceinline__ void ffma2(u64& d, u64 a, u64 b) {
    asm("fma.rn.f32x2 %0, %1, %2, %0;" : "+l"(d) : "l"(a), "l"(b));
}
__device__ __forceinline__ void upk2(float& lo, float& hi, u64 v) {
    asm("mov.b64 {%0, %1}, %2;" : "=f"(lo), "=f"(hi) : "l"(v));
}
__device__ __forceinline__ int detect64(const int* e32) {
    int z = 0;
#pragma unroll
    for (int j = 1; j <= 16; j++) z |= e32[2 * j + 1];
    return (z == 0) ? 1 : 0;
}

// mma.sync m16n8k16 row.col f32.bf16.bf16.f32 (baseline PTX, works on sm_103)
__device__ __forceinline__ void mma16816(float* d, const uint32_t* a, const uint32_t* b) {
    asm volatile(
        "mma.sync.aligned.m16n8k16.row.col.f32.bf16.bf16.f32 "
        "{%0,%1,%2,%3}, {%4,%5,%6,%7}, {%8,%9}, {%0,%1,%2,%3};"
        : "+f"(d[0]), "+f"(d[1]), "+f"(d[2]), "+f"(d[3])
        : "r"(a[0]), "r"(a[1]), "r"(a[2]), "r"(a[3]), "r"(b[0]), "r"(b[1]));
}

// ==================== CSR build ====================
__global__ void hist_kernel(const int* __restrict__ e32) {
    __shared__ int is64;
    if (threadIdx.x == 0) is64 = detect64(e32);
    __syncthreads();
    int i = blockIdx.x * blockDim.x + threadIdx.x;
    if (i >= ET) return;
    int d;
    if (i < NE) d = is64 ? e32[2 * (NE + i)] : e32[NE + i];
    else        d = i - NE;
    atomicAdd(&g_deg[d], 1);
}

__global__ void scan1() {
    __shared__ int sm[1024];
    int i = blockIdx.x * 1024 + threadIdx.x;
    int v = (i < NN) ? g_deg[i] : 0;
    sm[threadIdx.x] = v;
    __syncthreads();
    for (int off = 1; off < 1024; off <<= 1) {
        int t = (threadIdx.x >= off) ? sm[threadIdx.x - off] : 0;
        __syncthreads();
        sm[threadIdx.x] += t;
        __syncthreads();
    }
    if (i < NN) g_scan[i] = sm[threadIdx.x];
    if (threadIdx.x == 1023) g_bsum[blockIdx.x] = sm[1023];
}

__global__ void scan2() {
    __shared__ int sm[128];
    int t = threadIdx.x;
    int v = (t < NB) ? g_bsum[t] : 0;
    sm[t] = v;
    __syncthreads();
    for (int off = 1; off < 128; off <<= 1) {
        int a = (t >= off) ? sm[t - off] : 0;
        __syncthreads();
        sm[t] += a;
        __syncthreads();
    }
    if (t < NB) g_boff[t] = sm[t] - v;
}

__global__ void scan3() {
    int i = blockIdx.x * blockDim.x + threadIdx.x;
    if (i >= NN) return;
    int incl = g_scan[i] + g_boff[i >> 10];
    g_rp[i + 1] = incl;
    g_cur[i] = incl - g_deg[i];
    if (i == 0) g_rp[0] = 0;
}

__global__ void scatter(const int* __restrict__ e32) {
    __shared__ int is64;
    if (threadIdx.x == 0) is64 = detect64(e32);
    __syncthreads();
    int i = blockIdx.x * blockDim.x + threadIdx.x;
    if (i < NN) g_deg[i] = 0;
    if (i >= ET) return;
    int s, d;
    if (i < NE) {
        if (is64) { s = e32[2 * i]; d = e32[2 * (NE + i)]; }
        else      { s = e32[i];     d = e32[NE + i]; }
    } else {
        s = d = i - NE;
    }
    int pos = atomicAdd(&g_cur[d], 1);
    g_col[pos] = s;
}

// ==================== w_prep: W1^T -> bf16 hi/lo, linear [n][k] ====================
__global__ void w_prep(const float* __restrict__ W) {
    int i = blockIdx.x * blockDim.x + threadIdx.x;
    if (i >= 128 * 32) return;
    int n = i >> 5, k4 = (i & 31) * 4;
    float v0 = W[(k4 + 0) * 128 + n];
    float v1 = W[(k4 + 1) * 128 + n];
    float v2 = W[(k4 + 2) * 128 + n];
    float v3 = W[(k4 + 3) * 128 + n];
    __nv_bfloat162 h01 = __floats2bfloat162_rn(v0, v1);
    __nv_bfloat162 h23 = __floats2bfloat162_rn(v2, v3);
    __nv_bfloat162 l01 = __floats2bfloat162_rn(v0 - __low2float(h01), v1 - __high2float(h01));
    __nv_bfloat162 l23 = __floats2bfloat162_rn(v2 - __low2float(h23), v3 - __high2float(h23));
    uint32_t* hi = (uint32_t*)g_wt_hi;
    uint32_t* lo = (uint32_t*)g_wt_lo;
    int w32 = (n * 128 + k4) >> 1;
    hi[w32] = *(uint32_t*)&h01; hi[w32 + 1] = *(uint32_t*)&h23;
    lo[w32] = *(uint32_t*)&l01; lo[w32 + 1] = *(uint32_t*)&l23;
}

// ==================== GEMM1 via mma.sync: 64 rows/CTA, 2 CTAs/SM ====================
#define XSTR 136
#define SM_ATT 0
#define SM_ATD 512
#define SM_XHI 1024
#define SM_XLO (1024 + 17408)
#define SM_WHI (1024 + 34816)
#define SM_WLO (1024 + 69632)
#define G1_SMEM (1024 + 104448)

__global__ void __launch_bounds__(256, 2)
gemm1_tc(const float* __restrict__ x, const float* __restrict__ atts, const float* __restrict__ attd) {
    extern __shared__ char smem[];
    int t = threadIdx.x, lane = t & 31, wid = t >> 5;
    int row0 = blockIdx.x * 64;

    if (t < 128) {
        ((float*)(smem + SM_ATT))[t] = atts[t];
        ((float*)(smem + SM_ATD))[t] = attd[t];
    }

    for (int i = t; i < 2048; i += 256) {
        int r = i >> 5, c4 = (i & 31) * 4;
        int row = row0 + r;
        float4 v = (row < NN) ? *(const float4*)&x[row * 128 + c4]
                              : make_float4(0.f, 0.f, 0.f, 0.f);
        __nv_bfloat162 h01 = __floats2bfloat162_rn(v.x, v.y);
        __nv_bfloat162 h23 = __floats2bfloat162_rn(v.z, v.w);
        __nv_bfloat162 l01 = __floats2bfloat162_rn(v.x - __low2float(h01), v.y - __high2float(h01));
        __nv_bfloat162 l23 = __floats2bfloat162_rn(v.z - __low2float(h23), v.w - __high2float(h23));
        int off = (r * XSTR + c4) * 2;
        *(uint32_t*)(smem + SM_XHI + off)     = *(uint32_t*)&h01;
        *(uint32_t*)(smem + SM_XHI + off + 4) = *(uint32_t*)&h23;
        *(uint32_t*)(smem + SM_XLO + off)     = *(uint32_t*)&l01;
        *(uint32_t*)(smem + SM_XLO + off + 4) = *(uint32_t*)&l23;
    }
    for (int i = t; i < 2048; i += 256) {
        int n = i >> 4, k8 = (i & 15) * 8;
        int off = (n * XSTR + k8) * 2;
        *(uint4*)(smem + SM_WHI + off) = g_wt_hi[i];
        *(uint4*)(smem + SM_WLO + off) = g_wt_lo[i];
    }
    __syncthreads();

    int q = lane >> 2, c2 = (lane & 3) * 2;
    int slab = wid & 3, half = wid >> 2;
    int wrow = slab * 16;

    float acc[8][4];
#pragma unroll
    for (int j = 0; j < 8; j++)
#pragma unroll
        for (int u = 0; u < 4; u++) acc[j][u] = 0.f;

#pragma unroll
    for (int ks = 0; ks < 8; ks++) {
        int abase = ((wrow + q) * XSTR + ks * 16 + c2) * 2;
        uint32_t ah[4], al[4];
        ah[0] = *(uint32_t*)(smem + SM_XHI + abase);
        ah[1] = *(uint32_t*)(smem + SM_XHI + abase + 8 * XSTR * 2);
        ah[2] = *(uint32_t*)(smem + SM_XHI + abase + 16);
        ah[3] = *(uint32_t*)(smem + SM_XHI + abase + 8 * XSTR * 2 + 16);
        al[0] = *(uint32_t*)(smem + SM_XLO + abase);
        al[1] = *(uint32_t*)(smem + SM_XLO + abase + 8 * XSTR * 2);
        al[2] = *(uint32_t*)(smem + SM_XLO + abase + 16);
        al[3] = *(uint32_t*)(smem + SM_XLO + abase + 8 * XSTR * 2 + 16);
#pragma unroll
        for (int j = 0; j < 8; j++) {
            int nt = half * 8 + j;
            int bbase = ((nt * 8 + q) * XSTR + ks * 16 + c2) * 2;
            uint32_t bh[2], bl[2];
            bh[0] = *(uint32_t*)(smem + SM_WHI + bbase);
            bh[1] = *(uint32_t*)(smem + SM_WHI + bbase + 16);
            bl[0] = *(uint32_t*)(smem + SM_WLO + bbase);
            bl[1] = *(uint32_t*)(smem + SM_WLO + bbase + 16);
            mma16816(acc[j], ah, bh);
            mma16816(acc[j], ah, bl);
            mma16816(acc[j], al, bh);
        }
    }

    const float* satt = (const float*)(smem + SM_ATT);
    const float* satd = (const float*)(smem + SM_ATD);
    int rowA = row0 + wrow + q;
    int rowB = rowA + 8;
    float psA[4], pdA[4], psB[4], pdB[4];
#pragma unroll
    for (int h = 0; h < 4; h++) { psA[h] = pdA[h] = psB[h] = pdB[h] = 0.f; }

#pragma unroll
    for (int j = 0; j < 8; j++) {
        int nt = half * 8 + j;
        int col = nt * 8 + c2;
        int hl = j >> 1;
        float d0 = acc[j][0], d1 = acc[j][1], d2 = acc[j][2], d3 = acc[j][3];
        float t0 = satt[col], t1 = satt[col + 1];
        float u0 = satd[col], u1 = satd[col + 1];
        psA[hl] += d0 * t0 + d1 * t1; pdA[hl] += d0 * u0 + d1 * u1;
        psB[hl] += d2 * t0 + d3 * t1; pdB[hl] += d2 * u0 + d3 * u1;
        if (rowA < NN) *(float2*)&g_h1[rowA * 128 + col] = make_float2(d0, d1);
        if (rowB < NN) *(float2*)&g_h1[rowB * 128 + col] = make_float2(d2, d3);
    }
#pragma unroll
    for (int h = 0; h < 4; h++) {
        psA[h] += __shfl_xor_sync(0xffffffffu, psA[h], 1);
        psA[h] += __shfl_xor_sync(0xffffffffu, psA[h], 2);
        pdA[h] += __shfl_xor_sync(0xffffffffu, pdA[h], 1);
        pdA[h] += __shfl_xor_sync(0xffffffffu, pdA[h], 2);
        psB[h] += __shfl_xor_sync(0xffffffffu, psB[h], 1);
        psB[h] += __shfl_xor_sync(0xffffffffu, psB[h], 2);
        pdB[h] += __shfl_xor_sync(0xffffffffu, pdB[h], 1);
        pdB[h] += __shfl_xor_sync(0xffffffffu, pdB[h], 2);
    }
    int c = lane & 3;
    int h = half * 4 + c;
    if (rowA < NN) { g_as1[rowA * 8 + h] = psA[c]; g_ad1[rowA * 8 + h] = pdA[c]; }
    if (rowB < NN) { g_as1[rowB * 8 + h] = psB[c]; g_ad1[rowB * 8 + h] = pdB[c]; }
}

// ==================== fused layer1: single-pass, MLP-4 gather ====================
__global__ void l1_gather(const float* __restrict__ b1) {
    __shared__ float sex[8][8][33];
    int w = (blockIdx.x * blockDim.x + threadIdx.x) >> 5;
    int wid = (threadIdx.x >> 5) & 7;
    int lane = threadIdx.x & 31;
    if (w >= NN) return;
    int beg = g_rp[w], end = g_rp[w + 1];

    float4 ad0 = *(const float4*)&g_ad1[w * 8];
    float4 ad1v = *(const float4*)&g_ad1[w * 8 + 4];

    int h = lane >> 2;
    float dn[8] = {};
    float4 acc = make_float4(0.f, 0.f, 0.f, 0.f);

    for (int base = beg; base < end; base += 32) {
        int idx = base + lane;
        int sc = (idx < end) ? g_col[idx] : 0;
        float msk = (idx < end) ? 1.f : 0.f;
        {
            float4 s0 = *(const float4*)&g_as1[sc * 8];
            float4 s1 = *(const float4*)&g_as1[sc * 8 + 4];
            float e0 = __expf(lrelu(s0.x + ad0.x)) * msk;
            float e1 = __expf(lrelu(s0.y + ad0.y)) * msk;
            float e2 = __expf(lrelu(s0.z + ad0.z)) * msk;
            float e3 = __expf(lrelu(s0.w + ad0.w)) * msk;
            float e4 = __expf(lrelu(s1.x + ad1v.x)) * msk;
            float e5 = __expf(lrelu(s1.y + ad1v.y)) * msk;
            float e6 = __expf(lrelu(s1.z + ad1v.z)) * msk;
            float e7 = __expf(lrelu(s1.w + ad1v.w)) * msk;
            sex[wid][0][lane] = e0; dn[0] += e0;
            sex[wid][1][lane] = e1; dn[1] += e1;
            sex[wid][2][lane] = e2; dn[2] += e2;
            sex[wid][3][lane] = e3; dn[3] += e3;
            sex[wid][4][lane] = e4; dn[4] += e4;
            sex[wid][5][lane] = e5; dn[5] += e5;
            sex[wid][6][lane] = e6; dn[6] += e6;
            sex[wid][7][lane] = e7; dn[7] += e7;
        }
        __syncwarp();
        int n = min(32, end - base);
        int j = 0;
        for (; j + 4 <= n; j += 4) {
            int s0 = __shfl_sync(0xffffffffu, sc, j);
            int s1 = __shfl_sync(0xffffffffu, sc, j + 1);
            int s2 = __shfl_sync(0xffffffffu, sc, j + 2);
            int s3 = __shfl_sync(0xffffffffu, sc, j + 3);
            float a0 = sex[wid][h][j];
            float a1 = sex[wid][h][j + 1];
            float a2 = sex[wid][h][j + 2];
            float a3 = sex[wid][h][j + 3];
            float4 v0 = *(const float4*)&g_h1[s0 * 128 + lane * 4];
            float4 v1 = *(const float4*)&g_h1[s1 * 128 + lane * 4];
            float4 v2 = *(const float4*)&g_h1[s2 * 128 + lane * 4];
            float4 v3 = *(const float4*)&g_h1[s3 * 128 + lane * 4];
            acc.x += a0 * v0.x; acc.y += a0 * v0.y;
            acc.z += a0 * v0.z; acc.w += a0 * v0.w;
            acc.x += a1 * v1.x; acc.y += a1 * v1.y;
            acc.z += a1 * v1.z; acc.w += a1 * v1.w;
            acc.x += a2 * v2.x; acc.y += a2 * v2.y;
            acc.z += a2 * v2.z; acc.w += a2 * v2.w;
            acc.x += a3 * v3.x; acc.y += a3 * v3.y;
            acc.z += a3 * v3.z; acc.w += a3 * v3.w;
        }
        for (; j < n; j++) {
            int s0 = __shfl_sync(0xffffffffu, sc, j);
            float a0 = sex[wid][h][j];
            float4 v0 = *(const float4*)&g_h1[s0 * 128 + lane * 4];
            acc.x += a0 * v0.x; acc.y += a0 * v0.y;
            acc.z += a0 * v0.z; acc.w += a0 * v0.w;
        }
        __syncwarp();
    }

#pragma unroll
    for (int hh = 0; hh < 8; hh++)
        for (int off = 16; off; off >>= 1)
            dn[hh] += __shfl_xor_sync(0xffffffffu, dn[hh], off);
    float rdn = 1.f / (dn[h] + 1e-16f);

    float4 bb = *(const float4*)&b1[lane * 4];
    acc.x = acc.x * rdn + bb.x;
    acc.y = acc.y * rdn + bb.y;
    acc.z = acc.z * rdn + bb.z;
    acc.w = acc.w * rdn + bb.w;
    acc.x = acc.x > 0.f ? acc.x : expm1f(acc.x);
    acc.y = acc.y > 0.f ? acc.y : expm1f(acc.y);
    acc.z = acc.z > 0.f ? acc.z : expm1f(acc.z);
    acc.w = acc.w > 0.f ? acc.w : expm1f(acc.w);
    *(float4*)&g_o1[w * 128 + lane * 4] = acc;
}

// ==================== GEMM2 (128->40, LDS.128 f32x2) with fused a2 dots ====================
__global__ void gemm2_kernel(const float* __restrict__ W,
                             const float* __restrict__ atts, const float* __restrict__ attd) {
    extern __shared__ float sm[];
    float* xs = sm + 5120;
    float* sa = sm + 5120 + 8448;
    float* sd = sa + 64;
    int t = threadIdx.x;
    int ct = t % 10, rt = t / 10;
    int row0 = blockIdx.x * 64;

    for (int i = t; i < 5120; i += 160) {
        int k = i / 40, c = i % 40;
        sm[(k >> 2) * 160 + (c & 3) * 40 + (c >> 2) * 4 + (k & 3)] = W[i];
    }
    for (int i = t; i < 2048; i += 160) {
        int r = i >> 5, k4 = (i & 31) * 4;
        int row = row0 + r;
        float4 v = (row < NN) ? *(const float4*)&g_o1[row * 128 + k4]
                              : make_float4(0.f, 0.f, 0.f, 0.f);
        *(float4*)&xs[r * 132 + k4] = v;
    }
    if (t < 64) { sa[t] = 0.f; sd[t] = 0.f; }
    __syncthreads();

    u64 acc2[4][4];
#pragma unroll
    for (int i = 0; i < 4; i++)
#pragma unroll
        for (int c = 0; c < 4; c++) acc2[i][c] = 0ull;

#pragma unroll 2
    for (int kpp = 0; kpp < 32; kpp++) {
        const float* wb = sm + kpp * 160 + 4 * ct;
        ulonglong2 w0 = *(const ulonglong2*)(wb);
        ulonglong2 w1 = *(const ulonglong2*)(wb + 40);
        ulonglong2 w2 = *(const ulonglong2*)(wb + 80);
        ulonglong2 w3 = *(const ulonglong2*)(wb + 120);
#pragma unroll
        for (int i = 0; i < 4; i++) {
            ulonglong2 xp = *(const ulonglong2*)&xs[(rt * 4 + i) * 132 + 4 * kpp];
            ffma2(acc2[i][0], xp.x, w0.x); ffma2(acc2[i][0], xp.y, w0.y);
            ffma2(acc2[i][1], xp.x, w1.x); ffma2(acc2[i][1], xp.y, w1.y);
            ffma2(acc2[i][2], xp.x, w2.x); ffma2(acc2[i][2], xp.y, w2.y);
            ffma2(acc2[i][3], xp.x, w3.x); ffma2(acc2[i][3], xp.y, w3.y);
        }
    }

    float4 avs = *(const float4*)&atts[4 * ct];
    float4 avd = *(const float4*)&attd[4 * ct];
#pragma unroll
    for (int i = 0; i < 4; i++) {
        float a[4];
#pragma unroll
        for (int c = 0; c < 4; c++) {
            float lo, hi; upk2(lo, hi, acc2[i][c]);
            a[c] = lo + hi;
        }
        int row = row0 + rt * 4 + i;
        if (row < NN)
            *(float4*)&g_z[row * 40 + 4 * ct] = make_float4(a[0], a[1], a[2], a[3]);
        float ps = a[0] * avs.x + a[1] * avs.y + a[2] * avs.z + a[3] * avs.w;
        float pd = a[0] * avd.x + a[1] * avd.y + a[2] * avd.z + a[3] * avd.w;
        atomicAdd(&sa[rt * 4 + i], ps);
        atomicAdd(&sd[rt * 4 + i], pd);
    }
    __syncthreads();
    if (t < 64) {
        int row = row0 + t;
        if (row < NN) { g_as2[row] = sa[t]; g_ad2[row] = sd[t]; }
    }
}

// ==================== fused layer2: single-pass, MLP-4 + bias + log_softmax ====================
__global__ void l2_gather(float* __restrict__ out, const float* __restrict__ b2) {
    int w = (blockIdx.x * blockDim.x + threadIdx.x) >> 5;
    int lane = threadIdx.x & 31;
    if (w >= NN) return;
    int beg = g_rp[w], end = g_rp[w + 1];
    float adw = g_ad2[w];

    float dn = 0.f;
    float a1 = 0.f, a2 = 0.f;
    for (int base = beg; base < end; base += 32) {
        int idx = base + lane;
        int sc = (idx < end) ? g_col[idx] : 0;
        float ex = (idx < end) ? __expf(lrelu(g_as2[sc] + adw)) : 0.f;
        dn += ex;
        int n = min(32, end - base);
        int j = 0;
        for (; j + 4 <= n; j += 4) {
            float al0 = __shfl_sync(0xffffffffu, ex, j);
            float al1 = __shfl_sync(0xffffffffu, ex, j + 1);
            float al2 = __shfl_sync(0xffffffffu, ex, j + 2);
            float al3 = __shfl_sync(0xffffffffu, ex, j + 3);
            int s0 = __shfl_sync(0xffffffffu, sc, j);
            int s1 = __shfl_sync(0xffffffffu, sc, j + 1);
            int s2 = __shfl_sync(0xffffffffu, sc, j + 2);
            int s3 = __shfl_sync(0xffffffffu, sc, j + 3);
            float z00 = g_z[s0 * 40 + lane];
            float z10 = g_z[s1 * 40 + lane];
            float z20 = g_z[s2 * 40 + lane];
            float z30 = g_z[s3 * 40 + lane];
            float z01 = (lane < 8) ? g_z[s0 * 40 + 32 + lane] : 0.f;
            float z11 = (lane < 8) ? g_z[s1 * 40 + 32 + lane] : 0.f;
            float z21 = (lane < 8) ? g_z[s2 * 40 + 32 + lane] : 0.f;
            float z31 = (lane < 8) ? g_z[s3 * 40 + 32 + lane] : 0.f;
            a1 += al0 * z00 + al1 * z10 + al2 * z20 + al3 * z30;
            a2 += al0 * z01 + al1 * z11 + al2 * z21 + al3 * z31;
        }
        for (; j < n; j++) {
            float al0 = __shfl_sync(0xffffffffu, ex, j);
            int s0 = __shfl_sync(0xffffffffu, sc, j);
            a1 += al0 * g_z[s0 * 40 + lane];
            if (lane < 8) a2 += al0 * g_z[s0 * 40 + 32 + lane];
        }
    }
    for (int off = 16; off; off >>= 1)
        dn += __shfl_xor_sync(0xffffffffu, dn, off);
    float rdn = 1.f / (dn + 1e-16f);

    float v1 = a1 * rdn + b2[lane];
    float v2 = (lane < 8) ? a2 * rdn + b2[32 + lane] : -1e30f;
    float m = fmaxf(v1, v2);
    for (int o = 16; o; o >>= 1) m = fmaxf(m, __shfl_xor_sync(0xffffffffu, m, o));
    float s = expf(v1 - m) + ((lane < 8) ? expf(v2 - m) : 0.f);
    for (int o = 16; o; o >>= 1) s += __shfl_xor_sync(0xffffffffu, s, o);
    float ls = m + logf(s);
    out[w * 40 + lane] = v1 - ls;
    if (lane < 8) out[w * 40 + 32 + lane] = v2 - ls;
}

// ==================== launch ====================
extern "C" void kernel_launch(void* const* d_in, const int* in_sizes, int n_in,
                              void* d_out, int out_size) {
    const float* x   = (const float*)d_in[0];
    const int*   ei  = (const int*)d_in[1];
    const float* W1  = (const float*)d_in[2];
    const float* as1 = (const float*)d_in[3];
    const float* ad1 = (const float*)d_in[4];
    const float* b1  = (const float*)d_in[5];
    const float* W2  = (const float*)d_in[6];
    const float* as2 = (const float*)d_in[7];
    const float* ad2 = (const float*)d_in[8];
    const float* b2  = (const float*)d_in[9];
    float* out = (float*)d_out;

    static cudaStream_t sB = nullptr;
    static cudaEvent_t evF = nullptr, evJ = nullptr;
    if (!sB) {
        cudaStreamCreateWithFlags(&sB, cudaStreamNonBlocking);
        cudaEventCreateWithFlags(&evF, cudaEventDisableTiming);
        cudaEventCreateWithFlags(&evJ, cudaEventDisableTiming);
    }

    const int SM2 = (5120 + 64 * 132 + 128) * 4;
    cudaFuncSetAttribute(gemm1_tc, cudaFuncAttributeMaxDynamicSharedMemorySize, G1_SMEM);
    cudaFuncSetAttribute(gemm2_kernel, cudaFuncAttributeMaxDynamicSharedMemorySize, SM2);

    // fork: CSR build on side stream; W-prep + tensor-core gemm1 on main stream.
    cudaEventRecord(evF, 0);
    cudaStreamWaitEvent(sB, evF, 0);

    w_prep<<<16, 256>>>(W1);                                  // 0 (main)
    hist_kernel<<<(ET + 255) / 256, 256, 0, sB>>>(ei);        // 1
    scan1<<<NB, 1024, 0, sB>>>();                             // 2
    gemm1_tc<<<(NN + 63) / 64, 256, G1_SMEM>>>(x, as1, ad1);  // 3 <- profiled
    scan2<<<1, 128, 0, sB>>>();                               // 4
    scan3<<<(NN + 255) / 256, 256, 0, sB>>>();                // 5
    scatter<<<(ET + 255) / 256, 256, 0, sB>>>(ei);            // 6
    cudaEventRecord(evJ, sB);

    cudaStreamWaitEvent(0, evJ, 0);

    l1_gather<<<(NN * 32 + 255) / 256, 256>>>(b1);
    gemm2_kernel<<<(NN + 63) / 64, 160, SM2>>>(W2, as2, ad2);
    l2_gather<<<(NN * 32 + 255) / 256, 256>>>(out, b2);
}

// round 16
// speedup vs baseline: 1.3815x; 1.0281x over previous
#include <cuda_runtime.h>
#include <cuda_bf16.h>
#include <cuda_fp16.h>
#include <cstdint>

#define NN 100000
#define NE 1600000
#define ET (NE + NN)
#define NB 98   // ceil(NN/1024) scan blocks

typedef unsigned long long u64;

// -------- scratch (device globals: no allocations allowed) --------
__device__ int    g_col[ET];
__device__ int    g_deg[NN];
__device__ int    g_scan[NN];
__device__ int    g_bsum[NB];
__device__ int    g_boff[NB];
__device__ int    g_rp[NN + 1];
__device__ int    g_cur[NN];
__device__ uint4  g_wt_hi[2048];   // W1^T bf16 hi, linear [n][k] (128x128)
__device__ uint4  g_wt_lo[2048];   // W1^T bf16 lo
__device__ __half g_h1[NN * 128];  // layer1 features, fp16 (halves gather traffic)
__device__ float  g_as1[NN * 8];
__device__ float  g_ad1[NN * 8];
__device__ float  g_o1[NN * 128];
__device__ float  g_z[NN * 40];
__device__ float  g_as2[NN];
__device__ float  g_ad2[NN];

__device__ __forceinline__ float lrelu(float v) { return v > 0.f ? v : 0.2f * v; }

__device__ __forceinline__ void ffma2(u64& d, u64 a, u64 b) {
    asm("fma.rn.f32x2 %0, %1, %2, %0;" : "+l"(d) : "l"(a), "l"(b));
}
__device__ __forceinline__ void upk2(float& lo, float& hi, u64 v) {
    asm("mov.b64 {%0, %1}, %2;" : "=f"(lo), "=f"(hi) : "l"(v));
}
__device__ __forceinline__ int detect64(const int* e32) {
    int z = 0;
#pragma unroll
    for (int j = 1; j <= 16; j++) z |= e32[2 * j + 1];
    return (z == 0) ? 1 : 0;
}

// mma.sync m16n8k16 row.col f32.bf16.bf16.f32 (baseline PTX, works on sm_103)
__device__ __forceinline__ void mma16816(float* d, const uint32_t* a, const uint32_t* b) {
    asm volatile(
        "mma.sync.aligned.m16n8k16.row.col.f32.bf16.bf16.f32 "
        "{%0,%1,%2,%3}, {%4,%5,%6,%7}, {%8,%9}, {%0,%1,%2,%3};"
        : "+f"(d[0]), "+f"(d[1]), "+f"(d[2]), "+f"(d[3])
        : "r"(a[0]), "r"(a[1]), "r"(a[2]), "r"(a[3]), "r"(b[0]), "r"(b[1]));
}

// ==================== CSR build ====================
__global__ void hist_kernel(const int* __restrict__ e32) {
    __shared__ int is64;
    if (threadIdx.x == 0) is64 = detect64(e32);
    __syncthreads();
    int i = blockIdx.x * blockDim.x + threadIdx.x;
    if (i >= ET) return;
    int d;
    if (i < NE) d = is64 ? e32[2 * (NE + i)] : e32[NE + i];
    else        d = i - NE;
    atomicAdd(&g_deg[d], 1);
}

__global__ void scan1() {
    __shared__ int sm[1024];
    int i = blockIdx.x * 1024 + threadIdx.x;
    int v = (i < NN) ? g_deg[i] : 0;
    sm[threadIdx.x] = v;
    __syncthreads();
    for (int off = 1; off < 1024; off <<= 1) {
        int t = (threadIdx.x >= off) ? sm[threadIdx.x - off] : 0;
        __syncthreads();
        sm[threadIdx.x] += t;
        __syncthreads();
    }
    if (i < NN) g_scan[i] = sm[threadIdx.x];
    if (threadIdx.x == 1023) g_bsum[blockIdx.x] = sm[1023];
}

__global__ void scan2() {
    __shared__ int sm[128];
    int t = threadIdx.x;
    int v = (t < NB) ? g_bsum[t] : 0;
    sm[t] = v;
    __syncthreads();
    for (int off = 1; off < 128; off <<= 1) {
        int a = (t >= off) ? sm[t - off] : 0;
        __syncthreads();
        sm[t] += a;
        __syncthreads();
    }
    if (t < NB) g_boff[t] = sm[t] - v;
}

__global__ void scan3() {
    int i = blockIdx.x * blockDim.x + threadIdx.x;
    if (i >= NN) return;
    int incl = g_scan[i] + g_boff[i >> 10];
    g_rp[i + 1] = incl;
    g_cur[i] = incl - g_deg[i];
    if (i == 0) g_rp[0] = 0;
}

__global__ void scatter(const int* __restrict__ e32) {
    __shared__ int is64;
    if (threadIdx.x == 0) is64 = detect64(e32);
    __syncthreads();
    int i = blockIdx.x * blockDim.x + threadIdx.x;
    if (i < NN) g_deg[i] = 0;
    if (i >= ET) return;
    int s, d;
    if (i < NE) {
        if (is64) { s = e32[2 * i]; d = e32[2 * (NE + i)]; }
        else      { s = e32[i];     d = e32[NE + i]; }
    } else {
        s = d = i - NE;
    }
    int pos = atomicAdd(&g_cur[d], 1);
    g_col[pos] = s;
}

// ==================== w_prep: W1^T -> bf16 hi/lo, linear [n][k] ====================
__global__ void w_prep(const float* __restrict__ W) {
    int i = blockIdx.x * blockDim.x + threadIdx.x;
    if (i >= 128 * 32) return;
    int n = i >> 5, k4 = (i & 31) * 4;
    float v0 = W[(k4 + 0) * 128 + n];
    float v1 = W[(k4 + 1) * 128 + n];
    float v2 = W[(k4 + 2) * 128 + n];
    float v3 = W[(k4 + 3) * 128 + n];
    __nv_bfloat162 h01 = __floats2bfloat162_rn(v0, v1);
    __nv_bfloat162 h23 = __floats2bfloat162_rn(v2, v3);
    __nv_bfloat162 l01 = __floats2bfloat162_rn(v0 - __low2float(h01), v1 - __high2float(h01));
    __nv_bfloat162 l23 = __floats2bfloat162_rn(v2 - __low2float(h23), v3 - __high2float(h23));
    uint32_t* hi = (uint32_t*)g_wt_hi;
    uint32_t* lo = (uint32_t*)g_wt_lo;
    int w32 = (n * 128 + k4) >> 1;
    hi[w32] = *(uint32_t*)&h01; hi[w32 + 1] = *(uint32_t*)&h23;
    lo[w32] = *(uint32_t*)&l01; lo[w32 + 1] = *(uint32_t*)&l23;
}

// ==================== GEMM1 via mma.sync: 64 rows/CTA, 2 CTAs/SM ====================
#define XSTR 136
#define SM_ATT 0
#define SM_ATD 512
#define SM_XHI 1024
#define SM_XLO (1024 + 17408)
#define SM_WHI (1024 + 34816)
#define SM_WLO (1024 + 69632)
#define G1_SMEM (1024 + 104448)

__global__ void __launch_bounds__(256, 2)
gemm1_tc(const float* __restrict__ x, const float* __restrict__ atts, const float* __restrict__ attd) {
    extern __shared__ char smem[];
    int t = threadIdx.x, lane = t & 31, wid = t >> 5;
    int row0 = blockIdx.x * 64;

    if (t < 128) {
        ((float*)(smem + SM_ATT))[t] = atts[t];
        ((float*)(smem + SM_ATD))[t] = attd[t];
    }

    for (int i = t; i < 2048; i += 256) {
        int r = i >> 5, c4 = (i & 31) * 4;
        int row = row0 + r;
        float4 v = (row < NN) ? *(const float4*)&x[row * 128 + c4]
                              : make_float4(0.f, 0.f, 0.f, 0.f);
        __nv_bfloat162 h01 = __floats2bfloat162_rn(v.x, v.y);
        __nv_bfloat162 h23 = __floats2bfloat162_rn(v.z, v.w);
        __nv_bfloat162 l01 = __floats2bfloat162_rn(v.x - __low2float(h01), v.y - __high2float(h01));
        __nv_bfloat162 l23 = __floats2bfloat162_rn(v.z - __low2float(h23), v.w - __high2float(h23));
        int off = (r * XSTR + c4) * 2;
        *(uint32_t*)(smem + SM_XHI + off)     = *(uint32_t*)&h01;
        *(uint32_t*)(smem + SM_XHI + off + 4) = *(uint32_t*)&h23;
        *(uint32_t*)(smem + SM_XLO + off)     = *(uint32_t*)&l01;
        *(uint32_t*)(smem + SM_XLO + off + 4) = *(uint32_t*)&l23;
    }
    for (int i = t; i < 2048; i += 256) {
        int n = i >> 4, k8 = (i & 15) * 8;
        int off = (n * XSTR + k8) * 2;
        *(uint4*)(smem + SM_WHI + off) = g_wt_hi[i];
        *(uint4*)(smem + SM_WLO + off) = g_wt_lo[i];
    }
    __syncthreads();

    int q = lane >> 2, c2 = (lane & 3) * 2;
    int slab = wid & 3, half = wid >> 2;
    int wrow = slab * 16;

    float acc[8][4];
#pragma unroll
    for (int j = 0; j < 8; j++)
#pragma unroll
        for (int u = 0; u < 4; u++) acc[j][u] = 0.f;

#pragma unroll
    for (int ks = 0; ks < 8; ks++) {
        int abase = ((wrow + q) * XSTR + ks * 16 + c2) * 2;
        uint32_t ah[4], al[4];
        ah[0] = *(uint32_t*)(smem + SM_XHI + abase);
        ah[1] = *(uint32_t*)(smem + SM_XHI + abase + 8 * XSTR * 2);
        ah[2] = *(uint32_t*)(smem + SM_XHI + abase + 16);
        ah[3] = *(uint32_t*)(smem + SM_XHI + abase + 8 * XSTR * 2 + 16);
        al[0] = *(uint32_t*)(smem + SM_XLO + abase);
        al[1] = *(uint32_t*)(smem + SM_XLO + abase + 8 * XSTR * 2);
        al[2] = *(uint32_t*)(smem + SM_XLO + abase + 16);
        al[3] = *(uint32_t*)(smem + SM_XLO + abase + 8 * XSTR * 2 + 16);
#pragma unroll
        for (int j = 0; j < 8; j++) {
            int nt = half * 8 + j;
            int bbase = ((nt * 8 + q) * XSTR + ks * 16 + c2) * 2;
            uint32_t bh[2], bl[2];
            bh[0] = *(uint32_t*)(smem + SM_WHI + bbase);
            bh[1] = *(uint32_t*)(smem + SM_WHI + bbase + 16);
            bl[0] = *(uint32_t*)(smem + SM_WLO + bbase);
            bl[1] = *(uint32_t*)(smem + SM_WLO + bbase + 16);
            mma16816(acc[j], ah, bh);
            mma16816(acc[j], ah, bl);
            mma16816(acc[j], al, bh);
        }
    }

    const float* satt = (const float*)(smem + SM_ATT);
    const float* satd = (const float*)(smem + SM_ATD);
    int rowA = row0 + wrow + q;
    int rowB = rowA + 8;
    float psA[4], pdA[4], psB[4], pdB[4];
#pragma unroll
    for (int h = 0; h < 4; h++) { psA[h] = pdA[h] = psB[h] = pdB[h] = 0.f; }

#pragma unroll
    for (int j = 0; j < 8; j++) {
        int nt = half * 8 + j;
        int col = nt * 8 + c2;
        int hl = j >> 1;
        float d0 = acc[j][0], d1 = acc[j][1], d2 = acc[j][2], d3 = acc[j][3];
        float t0 = satt[col], t1 = satt[col + 1];
        float u0 = satd[col], u1 = satd[col + 1];
        psA[hl] += d0 * t0 + d1 * t1; pdA[hl] += d0 * u0 + d1 * u1;
        psB[hl] += d2 * t0 + d3 * t1; pdB[hl] += d2 * u0 + d3 * u1;
        if (rowA < NN) {
            __half2 p = __floats2half2_rn(d0, d1);
            *(uint32_t*)&g_h1[rowA * 128 + col] = *(uint32_t*)&p;
        }
        if (rowB < NN) {
            __half2 p = __floats2half2_rn(d2, d3);
            *(uint32_t*)&g_h1[rowB * 128 + col] = *(uint32_t*)&p;
        }
    }
#pragma unroll
    for (int h = 0; h < 4; h++) {
        psA[h] += __shfl_xor_sync(0xffffffffu, psA[h], 1);
        psA[h] += __shfl_xor_sync(0xffffffffu, psA[h], 2);
        pdA[h] += __shfl_xor_sync(0xffffffffu, pdA[h], 1);
        pdA[h] += __shfl_xor_sync(0xffffffffu, pdA[h], 2);
        psB[h] += __shfl_xor_sync(0xffffffffu, psB[h], 1);
        psB[h] += __shfl_xor_sync(0xffffffffu, psB[h], 2);
        pdB[h] += __shfl_xor_sync(0xffffffffu, pdB[h], 1);
        pdB[h] += __shfl_xor_sync(0xffffffffu, pdB[h], 2);
    }
    int c = lane & 3;
    int h = half * 4 + c;
    if (rowA < NN) { g_as1[rowA * 8 + h] = psA[c]; g_ad1[rowA * 8 + h] = pdA[c]; }
    if (rowB < NN) { g_as1[rowB * 8 + h] = psB[c]; g_ad1[rowB * 8 + h] = pdB[c]; }
}

// ==================== fused layer1: single-pass, MLP-4 gather (fp16 h1) ====================
__global__ void l1_gather(const float* __restrict__ b1) {
    __shared__ float sex[8][8][33];
    int w = (blockIdx.x * blockDim.x + threadIdx.x) >> 5;
    int wid = (threadIdx.x >> 5) & 7;
    int lane = threadIdx.x & 31;
    if (w >= NN) return;
    int beg = g_rp[w], end = g_rp[w + 1];

    float4 ad0 = *(const float4*)&g_ad1[w * 8];
    float4 ad1v = *(const float4*)&g_ad1[w * 8 + 4];

    int h = lane >> 2;
    float dn[8] = {};
    float4 acc = make_float4(0.f, 0.f, 0.f, 0.f);

    for (int base = beg; base < end; base += 32) {
        int idx = base + lane;
        int sc = (idx < end) ? g_col[idx] : 0;
        float msk = (idx < end) ? 1.f : 0.f;
        {
            float4 s0 = *(const float4*)&g_as1[sc * 8];
            float4 s1 = *(const float4*)&g_as1[sc * 8 + 4];
            float e0 = __expf(lrelu(s0.x + ad0.x)) * msk;
            float e1 = __expf(lrelu(s0.y + ad0.y)) * msk;
            float e2 = __expf(lrelu(s0.z + ad0.z)) * msk;
            float e3 = __expf(lrelu(s0.w + ad0.w)) * msk;
            float e4 = __expf(lrelu(s1.x + ad1v.x)) * msk;
            float e5 = __expf(lrelu(s1.y + ad1v.y)) * msk;
            float e6 = __expf(lrelu(s1.z + ad1v.z)) * msk;
            float e7 = __expf(lrelu(s1.w + ad1v.w)) * msk;
            sex[wid][0][lane] = e0; dn[0] += e0;
            sex[wid][1][lane] = e1; dn[1] += e1;
            sex[wid][2][lane] = e2; dn[2] += e2;
            sex[wid][3][lane] = e3; dn[3] += e3;
            sex[wid][4][lane] = e4; dn[4] += e4;
            sex[wid][5][lane] = e5; dn[5] += e5;
            sex[wid][6][lane] = e6; dn[6] += e6;
            sex[wid][7][lane] = e7; dn[7] += e7;
        }
        __syncwarp();
        int n = min(32, end - base);
        int j = 0;
        for (; j + 4 <= n; j += 4) {
            int s0 = __shfl_sync(0xffffffffu, sc, j);
            int s1 = __shfl_sync(0xffffffffu, sc, j + 1);
            int s2 = __shfl_sync(0xffffffffu, sc, j + 2);
            int s3 = __shfl_sync(0xffffffffu, sc, j + 3);
            float a0 = sex[wid][h][j];
            float a1 = sex[wid][h][j + 1];
            float a2 = sex[wid][h][j + 2];
            float a3 = sex[wid][h][j + 3];
            uint2 r0 = *(const uint2*)&g_h1[s0 * 128 + lane * 4];
            uint2 r1 = *(const uint2*)&g_h1[s1 * 128 + lane * 4];
            uint2 r2 = *(const uint2*)&g_h1[s2 * 128 + lane * 4];
            uint2 r3 = *(const uint2*)&g_h1[s3 * 128 + lane * 4];
            float2 f0a = __half22float2(*(__half2*)&r0.x), f0b = __half22float2(*(__half2*)&r0.y);
            float2 f1a = __half22float2(*(__half2*)&r1.x), f1b = __half22float2(*(__half2*)&r1.y);
            float2 f2a = __half22float2(*(__half2*)&r2.x), f2b = __half22float2(*(__half2*)&r2.y);
            float2 f3a = __half22float2(*(__half2*)&r3.x), f3b = __half22float2(*(__half2*)&r3.y);
            acc.x += a0 * f0a.x; acc.y += a0 * f0a.y;
            acc.z += a0 * f0b.x; acc.w += a0 * f0b.y;
            acc.x += a1 * f1a.x; acc.y += a1 * f1a.y;
            acc.z += a1 * f1b.x; acc.w += a1 * f1b.y;
            acc.x += a2 * f2a.x; acc.y += a2 * f2a.y;
            acc.z += a2 * f2b.x; acc.w += a2 * f2b.y;
            acc.x += a3 * f3a.x; acc.y += a3 * f3a.y;
            acc.z += a3 * f3b.x; acc.w += a3 * f3b.y;
        }
        for (; j < n; j++) {
            int s0 = __shfl_sync(0xffffffffu, sc, j);
            float a0 = sex[wid][h][j];
            uint2 r0 = *(const uint2*)&g_h1[s0 * 128 + lane * 4];
            float2 f0a = __half22float2(*(__half2*)&r0.x), f0b = __half22float2(*(__half2*)&r0.y);
            acc.x += a0 * f0a.x; acc.y += a0 * f0a.y;
            acc.z += a0 * f0b.x; acc.w += a0 * f0b.y;
        }
        __syncwarp();
    }

#pragma unroll
    for (int hh = 0; hh < 8; hh++)
        for (int off = 16; off; off >>= 1)
            dn[hh] += __shfl_xor_sync(0xffffffffu, dn[hh], off);
    float rdn = 1.f / (dn[h] + 1e-16f);

    float4 bb = *(const float4*)&b1[lane * 4];
    acc.x = acc.x * rdn + bb.x;
    acc.y = acc.y * rdn + bb.y;
    acc.z = acc.z * rdn + bb.z;
    acc.w = acc.w * rdn + bb.w;
    acc.x = acc.x > 0.f ? acc.x : expm1f(acc.x);
    acc.y = acc.y > 0.f ? acc.y : expm1f(acc.y);
    acc.z = acc.z > 0.f ? acc.z : expm1f(acc.z);
    acc.w = acc.w > 0.f ? acc.w : expm1f(acc.w);
    *(float4*)&g_o1[w * 128 + lane * 4] = acc;
}

// ==================== GEMM2 (128->40, LDS.128 f32x2) with fused a2 dots ====================
__global__ void gemm2_kernel(const float* __restrict__ W,
                             const float* __restrict__ atts, const float* __restrict__ attd) {
    extern __shared__ float sm[];
    float* xs = sm + 5120;
    float* sa = sm + 5120 + 8448;
    float* sd = sa + 64;
    int t = threadIdx.x;
    int ct = t % 10, rt = t / 10;
    int row0 = blockIdx.x * 64;

    for (int i = t; i < 5120; i += 160) {
        int k = i / 40, c = i % 40;
        sm[(k >> 2) * 160 + (c & 3) * 40 + (c >> 2) * 4 + (k & 3)] = W[i];
    }
    for (int i = t; i < 2048; i += 160) {
        int r = i >> 5, k4 = (i & 31) * 4;
        int row = row0 + r;
        float4 v = (row < NN) ? *(const float4*)&g_o1[row * 128 + k4]
                              : make_float4(0.f, 0.f, 0.f, 0.f);
        *(float4*)&xs[r * 132 + k4] = v;
    }
    if (t < 64) { sa[t] = 0.f; sd[t] = 0.f; }
    __syncthreads();

    u64 acc2[4][4];
#pragma unroll
    for (int i = 0; i < 4; i++)
#pragma unroll
        for (int c = 0; c < 4; c++) acc2[i][c] = 0ull;

#pragma unroll 2
    for (int kpp = 0; kpp < 32; kpp++) {
        const float* wb = sm + kpp * 160 + 4 * ct;
        ulonglong2 w0 = *(const ulonglong2*)(wb);
        ulonglong2 w1 = *(const ulonglong2*)(wb + 40);
        ulonglong2 w2 = *(const ulonglong2*)(wb + 80);
        ulonglong2 w3 = *(const ulonglong2*)(wb + 120);
#pragma unroll
        for (int i = 0; i < 4; i++) {
            ulonglong2 xp = *(const ulonglong2*)&xs[(rt * 4 + i) * 132 + 4 * kpp];
            ffma2(acc2[i][0], xp.x, w0.x); ffma2(acc2[i][0], xp.y, w0.y);
            ffma2(acc2[i][1], xp.x, w1.x); ffma2(acc2[i][1], xp.y, w1.y);
            ffma2(acc2[i][2], xp.x, w2.x); ffma2(acc2[i][2], xp.y, w2.y);
            ffma2(acc2[i][3], xp.x, w3.x); ffma2(acc2[i][3], xp.y, w3.y);
        }
    }

    float4 avs = *(const float4*)&atts[4 * ct];
    float4 avd = *(const float4*)&attd[4 * ct];
#pragma unroll
    for (int i = 0; i < 4; i++) {
        float a[4];
#pragma unroll
        for (int c = 0; c < 4; c++) {
            float lo, hi; upk2(lo, hi, acc2[i][c]);
            a[c] = lo + hi;
        }
        int row = row0 + rt * 4 + i;
        if (row < NN)
            *(float4*)&g_z[row * 40 + 4 * ct] = make_float4(a[0], a[1], a[2], a[3]);
        float ps = a[0] * avs.x + a[1] * avs.y + a[2] * avs.z + a[3] * avs.w;
        float pd = a[0] * avd.x + a[1] * avd.y + a[2] * avd.z + a[3] * avd.w;
        atomicAdd(&sa[rt * 4 + i], ps);
        atomicAdd(&sd[rt * 4 + i], pd);
    }
    __syncthreads();
    if (t < 64) {
        int row = row0 + t;
        if (row < NN) { g_as2[row] = sa[t]; g_ad2[row] = sd[t]; }
    }
}

// ==================== fused layer2: single-pass, MLP-4 + bias + log_softmax ====================
__global__ void l2_gather(float* __restrict__ out, const float* __restrict__ b2) {
    int w = (blockIdx.x * blockDim.x + threadIdx.x) >> 5;
    int lane = threadIdx.x & 31;
    if (w >= NN) return;
    int beg = g_rp[w], end = g_rp[w + 1];
    float adw = g_ad2[w];

    float dn = 0.f;
    float a1 = 0.f, a2 = 0.f;
    for (int base = beg; base < end; base += 32) {
        int idx = base + lane;
        int sc = (idx < end) ? g_col[idx] : 0;
        float ex = (idx < end) ? __expf(lrelu(g_as2[sc] + adw)) : 0.f;
        dn += ex;
        int n = min(32, end - base);
        int j = 0;
        for (; j + 4 <= n; j += 4) {
            float al0 = __shfl_sync(0xffffffffu, ex, j);
            float al1 = __shfl_sync(0xffffffffu, ex, j + 1);
            float al2 = __shfl_sync(0xffffffffu, ex, j + 2);
            float al3 = __shfl_sync(0xffffffffu, ex, j + 3);
            int s0 = __shfl_sync(0xffffffffu, sc, j);
            int s1 = __shfl_sync(0xffffffffu, sc, j + 1);
            int s2 = __shfl_sync(0xffffffffu, sc, j + 2);
            int s3 = __shfl_sync(0xffffffffu, sc, j + 3);
            float z00 = g_z[s0 * 40 + lane];
            float z10 = g_z[s1 * 40 + lane];
            float z20 = g_z[s2 * 40 + lane];
            float z30 = g_z[s3 * 40 + lane];
            float z01 = (lane < 8) ? g_z[s0 * 40 + 32 + lane] : 0.f;
            float z11 = (lane < 8) ? g_z[s1 * 40 + 32 + lane] : 0.f;
            float z21 = (lane < 8) ? g_z[s2 * 40 + 32 + lane] : 0.f;
            float z31 = (lane < 8) ? g_z[s3 * 40 + 32 + lane] : 0.f;
            a1 += al0 * z00 + al1 * z10 + al2 * z20 + al3 * z30;
            a2 += al0 * z01 + al1 * z11 + al2 * z21 + al3 * z31;
        }
        for (; j < n; j++) {
            float al0 = __shfl_sync(0xffffffffu, ex, j);
            int s0 = __shfl_sync(0xffffffffu, sc, j);
            a1 += al0 * g_z[s0 * 40 + lane];
            if (lane < 8) a2 += al0 * g_z[s0 * 40 + 32 + lane];
        }
    }
    for (int off = 16; off; off >>= 1)
        dn += __shfl_xor_sync(0xffffffffu, dn, off);
    float rdn = 1.f / (dn + 1e-16f);

    float v1 = a1 * rdn + b2[lane];
    float v2 = (lane < 8) ? a2 * rdn + b2[32 + lane] : -1e30f;
    float m = fmaxf(v1, v2);
    for (int o = 16; o; o >>= 1) m = fmaxf(m, __shfl_xor_sync(0xffffffffu, m, o));
    float s = expf(v1 - m) + ((lane < 8) ? expf(v2 - m) : 0.f);
    for (int o = 16; o; o >>= 1) s += __shfl_xor_sync(0xffffffffu, s, o);
    float ls = m + logf(s);
    out[w * 40 + lane] = v1 - ls;
    if (lane < 8) out[w * 40 + 32 + lane] = v2 - ls;
}

// ==================== launch ====================
extern "C" void kernel_launch(void* const* d_in, const int* in_sizes, int n_in,
                              void* d_out, int out_size) {
    const float* x   = (const float*)d_in[0];
    const int*   ei  = (const int*)d_in[1];
    const float* W1  = (const float*)d_in[2];
    const float* as1 = (const float*)d_in[3];
    const float* ad1 = (const float*)d_in[4];
    const float* b1  = (const float*)d_in[5];
    const float* W2  = (const float*)d_in[6];
    const float* as2 = (const float*)d_in[7];
    const float* ad2 = (const float*)d_in[8];
    const float* b2  = (const float*)d_in[9];
    float* out = (float*)d_out;

    static cudaStream_t sB = nullptr;
    static cudaEvent_t evF = nullptr, evJ = nullptr;
    if (!sB) {
        cudaStreamCreateWithFlags(&sB, cudaStreamNonBlocking);
        cudaEventCreateWithFlags(&evF, cudaEventDisableTiming);
        cudaEventCreateWithFlags(&evJ, cudaEventDisableTiming);
    }

    const int SM2 = (5120 + 64 * 132 + 128) * 4;
    cudaFuncSetAttribute(gemm1_tc, cudaFuncAttributeMaxDynamicSharedMemorySize, G1_SMEM);
    cudaFuncSetAttribute(gemm2_kernel, cudaFuncAttributeMaxDynamicSharedMemorySize, SM2);

    // fork: CSR build on side stream; W-prep + tensor-core gemm1 on main stream.
    cudaEventRecord(evF, 0);
    cudaStreamWaitEvent(sB, evF, 0);

    w_prep<<<16, 256>>>(W1);                                  // 0 (main)
    hist_kernel<<<(ET + 255) / 256, 256, 0, sB>>>(ei);        // 1
    scan1<<<NB, 1024, 0, sB>>>();                             // 2
    gemm1_tc<<<(NN + 63) / 64, 256, G1_SMEM>>>(x, as1, ad1);  // 3 <- profiled
    scan2<<<1, 128, 0, sB>>>();                               // 4
    scan3<<<(NN + 255) / 256, 256, 0, sB>>>();                // 5
    scatter<<<(ET + 255) / 256, 256, 0, sB>>>(ei);            // 6
    cudaEventRecord(evJ, sB);

    cudaStreamWaitEvent(0, evJ, 0);

    l1_gather<<<(NN * 32 + 255) / 256, 256>>>(b1);
    gemm2_kernel<<<(NN + 63) / 64, 160, SM2>>>(W2, as2, ad2);
    l2_gather<<<(NN * 32 + 255) / 256, 256>>>(out, b2);
}

// round 17
// speedup vs baseline: 1.4167x; 1.0255x over previous
#include <cuda_runtime.h>
#include <cuda_bf16.h>
#include <cuda_fp16.h>
#include <cstdint>

#define NN 100000
#define NE 1600000
#define ET (NE + NN)
#define NB 98     // ceil(NN/1024) scan blocks
#define N1 50048  // pipeline split point (64-aligned)

typedef unsigned long long u64;

// -------- scratch (device globals: no allocations allowed) --------
__device__ int    g_col[ET];
__device__ int    g_deg[NN];
__device__ int    g_scan[NN];
__device__ int    g_bsum[NB];
__device__ int    g_boff[NB];
__device__ int    g_rp[NN + 1];
__device__ int    g_cur[NN];
__device__ uint4  g_wt_hi[2048];   // W1^T bf16 hi, linear [n][k] (128x128)
__device__ uint4  g_wt_lo[2048];   // W1^T bf16 lo
__device__ __half g_h1[NN * 128];  // layer1 features, fp16
__device__ float  g_as1[NN * 8];
__device__ float  g_ad1[NN * 8];
__device__ __half g_o1h[NN * 128]; // layer1 out (bias+elu), fp16
__device__ float  g_z[NN * 40];
__device__ float  g_as2[NN];
__device__ float  g_ad2[NN];

__device__ __forceinline__ float lrelu(float v) { return v > 0.f ? v : 0.2f * v; }

__device__ __forceinline__ void ffma2(u64& d, u64 a, u64 b) {
    asm("fma.rn.f32x2 %0, %1, %2, %0;" : "+l"(d) : "l"(a), "l"(b));
}
__device__ __forceinline__ void upk2(float& lo, float& hi, u64 v) {
    asm("mov.b64 {%0, %1}, %2;" : "=f"(lo), "=f"(hi) : "l"(v));
}
__device__ __forceinline__ int detect64(const int* e32) {
    int z = 0;
#pragma unroll
    for (int j = 1; j <= 16; j++) z |= e32[2 * j + 1];
    return (z == 0) ? 1 : 0;
}

// mma.sync m16n8k16 row.col f32.bf16.bf16.f32 (baseline PTX, works on sm_103)
__device__ __forceinline__ void mma16816(float* d, const uint32_t* a, const uint32_t* b) {
    asm volatile(
        "mma.sync.aligned.m16n8k16.row.col.f32.bf16.bf16.f32 "
        "{%0,%1,%2,%3}, {%4,%5,%6,%7}, {%8,%9}, {%0,%1,%2,%3};"
        : "+f"(d[0]), "+f"(d[1]), "+f"(d[2]), "+f"(d[3])
        : "r"(a[0]), "r"(a[1]), "r"(a[2]), "r"(a[3]), "r"(b[0]), "r"(b[1]));
}

// ==================== CSR build ====================
__global__ void hist_kernel(const int* __restrict__ e32) {
    __shared__ int is64;
    if (threadIdx.x == 0) is64 = detect64(e32);
    __syncthreads();
    int i = blockIdx.x * blockDim.x + threadIdx.x;
    if (i >= ET) return;
    int d;
    if (i < NE) d = is64 ? e32[2 * (NE + i)] : e32[NE + i];
    else        d = i - NE;
    atomicAdd(&g_deg[d], 1);
}

__global__ void scan1() {
    __shared__ int sm[1024];
    int i = blockIdx.x * 1024 + threadIdx.x;
    int v = (i < NN) ? g_deg[i] : 0;
    sm[threadIdx.x] = v;
    __syncthreads();
    for (int off = 1; off < 1024; off <<= 1) {
        int t = (threadIdx.x >= off) ? sm[threadIdx.x - off] : 0;
        __syncthreads();
        sm[threadIdx.x] += t;
        __syncthreads();
    }
    if (i < NN) g_scan[i] = sm[threadIdx.x];
    if (threadIdx.x == 1023) g_bsum[blockIdx.x] = sm[1023];
}

__global__ void scan2() {
    __shared__ int sm[128];
    int t = threadIdx.x;
    int v = (t < NB) ? g_bsum[t] : 0;
    sm[t] = v;
    __syncthreads();
    for (int off = 1; off < 128; off <<= 1) {
        int a = (t >= off) ? sm[t - off] : 0;
        __syncthreads();
        sm[t] += a;
        __syncthreads();
    }
    if (t < NB) g_boff[t] = sm[t] - v;
}

__global__ void scan3() {
    int i = blockIdx.x * blockDim.x + threadIdx.x;
    if (i >= NN) return;
    int incl = g_scan[i] + g_boff[i >> 10];
    g_rp[i + 1] = incl;
    g_cur[i] = incl - g_deg[i];
    if (i == 0) g_rp[0] = 0;
}

__global__ void scatter(const int* __restrict__ e32) {
    __shared__ int is64;
    if (threadIdx.x == 0) is64 = detect64(e32);
    __syncthreads();
    int i = blockIdx.x * blockDim.x + threadIdx.x;
    if (i < NN) g_deg[i] = 0;
    if (i >= ET) return;
    int s, d;
    if (i < NE) {
        if (is64) { s = e32[2 * i]; d = e32[2 * (NE + i)]; }
        else      { s = e32[i];     d = e32[NE + i]; }
    } else {
        s = d = i - NE;
    }
    int pos = atomicAdd(&g_cur[d], 1);
    g_col[pos] = s;
}

// ==================== w_prep: W1^T -> bf16 hi/lo, linear [n][k] ====================
__global__ void w_prep(const float* __restrict__ W) {
    int i = blockIdx.x * blockDim.x + threadIdx.x;
    if (i >= 128 * 32) return;
    int n = i >> 5, k4 = (i & 31) * 4;
    float v0 = W[(k4 + 0) * 128 + n];
    float v1 = W[(k4 + 1) * 128 + n];
    float v2 = W[(k4 + 2) * 128 + n];
    float v3 = W[(k4 + 3) * 128 + n];
    __nv_bfloat162 h01 = __floats2bfloat162_rn(v0, v1);
    __nv_bfloat162 h23 = __floats2bfloat162_rn(v2, v3);
    __nv_bfloat162 l01 = __floats2bfloat162_rn(v0 - __low2float(h01), v1 - __high2float(h01));
    __nv_bfloat162 l23 = __floats2bfloat162_rn(v2 - __low2float(h23), v3 - __high2float(h23));
    uint32_t* hi = (uint32_t*)g_wt_hi;
    uint32_t* lo = (uint32_t*)g_wt_lo;
    int w32 = (n * 128 + k4) >> 1;
    hi[w32] = *(uint32_t*)&h01; hi[w32 + 1] = *(uint32_t*)&h23;
    lo[w32] = *(uint32_t*)&l01; lo[w32 + 1] = *(uint32_t*)&l23;
}

// ==================== GEMM1 via mma.sync: 64 rows/CTA, 2 CTAs/SM ====================
#define XSTR 136
#define SM_ATT 0
#define SM_ATD 512
#define SM_XHI 1024
#define SM_XLO (1024 + 17408)
#define SM_WHI (1024 + 34816)
#define SM_WLO (1024 + 69632)
#define G1_SMEM (1024 + 104448)

__global__ void __launch_bounds__(256, 2)
gemm1_tc(const float* __restrict__ x, const float* __restrict__ atts, const float* __restrict__ attd) {
    extern __shared__ char smem[];
    int t = threadIdx.x, lane = t & 31, wid = t >> 5;
    int row0 = blockIdx.x * 64;

    if (t < 128) {
        ((float*)(smem + SM_ATT))[t] = atts[t];
        ((float*)(smem + SM_ATD))[t] = attd[t];
    }

    for (int i = t; i < 2048; i += 256) {
        int r = i >> 5, c4 = (i & 31) * 4;
        int row = row0 + r;
        float4 v = (row < NN) ? *(const float4*)&x[row * 128 + c4]
                              : make_float4(0.f, 0.f, 0.f, 0.f);
        __nv_bfloat162 h01 = __floats2bfloat162_rn(v.x, v.y);
        __nv_bfloat162 h23 = __floats2bfloat162_rn(v.z, v.w);
        __nv_bfloat162 l01 = __floats2bfloat162_rn(v.x - __low2float(h01), v.y - __high2float(h01));
        __nv_bfloat162 l23 = __floats2bfloat162_rn(v.z - __low2float(h23), v.w - __high2float(h23));
        int off = (r * XSTR + c4) * 2;
        *(uint32_t*)(smem + SM_XHI + off)     = *(uint32_t*)&h01;
        *(uint32_t*)(smem + SM_XHI + off + 4) = *(uint32_t*)&h23;
        *(uint32_t*)(smem + SM_XLO + off)     = *(uint32_t*)&l01;
        *(uint32_t*)(smem + SM_XLO + off + 4) = *(uint32_t*)&l23;
    }
    for (int i = t; i < 2048; i += 256) {
        int n = i >> 4, k8 = (i & 15) * 8;
        int off = (n * XSTR + k8) * 2;
        *(uint4*)(smem + SM_WHI + off) = g_wt_hi[i];
        *(uint4*)(smem + SM_WLO + off) = g_wt_lo[i];
    }
    __syncthreads();

    int q = lane >> 2, c2 = (lane & 3) * 2;
    int slab = wid & 3, half = wid >> 2;
    int wrow = slab * 16;

    float acc[8][4];
#pragma unroll
    for (int j = 0; j < 8; j++)
#pragma unroll
        for (int u = 0; u < 4; u++) acc[j][u] = 0.f;

#pragma unroll
    for (int ks = 0; ks < 8; ks++) {
        int abase = ((wrow + q) * XSTR + ks * 16 + c2) * 2;
        uint32_t ah[4], al[4];
        ah[0] = *(uint32_t*)(smem + SM_XHI + abase);
        ah[1] = *(uint32_t*)(smem + SM_XHI + abase + 8 * XSTR * 2);
        ah[2] = *(uint32_t*)(smem + SM_XHI + abase + 16);
        ah[3] = *(uint32_t*)(smem + SM_XHI + abase + 8 * XSTR * 2 + 16);
        al[0] = *(uint32_t*)(smem + SM_XLO + abase);
        al[1] = *(uint32_t*)(smem + SM_XLO + abase + 8 * XSTR * 2);
        al[2] = *(uint32_t*)(smem + SM_XLO + abase + 16);
        al[3] = *(uint32_t*)(smem + SM_XLO + abase + 8 * XSTR * 2 + 16);
#pragma unroll
        for (int j = 0; j < 8; j++) {
            int nt = half * 8 + j;
            int bbase = ((nt * 8 + q) * XSTR + ks * 16 + c2) * 2;
            uint32_t bh[2], bl[2];
            bh[0] = *(uint32_t*)(smem + SM_WHI + bbase);
            bh[1] = *(uint32_t*)(smem + SM_WHI + bbase + 16);
            bl[0] = *(uint32_t*)(smem + SM_WLO + bbase);
            bl[1] = *(uint32_t*)(smem + SM_WLO + bbase + 16);
            mma16816(acc[j], ah, bh);
            mma16816(acc[j], ah, bl);
            mma16816(acc[j], al, bh);
        }
    }

    const float* satt = (const float*)(smem + SM_ATT);
    const float* satd = (const float*)(smem + SM_ATD);
    int rowA = row0 + wrow + q;
    int rowB = rowA + 8;
    float psA[4], pdA[4], psB[4], pdB[4];
#pragma unroll
    for (int h = 0; h < 4; h++) { psA[h] = pdA[h] = psB[h] = pdB[h] = 0.f; }

#pragma unroll
    for (int j = 0; j < 8; j++) {
        int nt = half * 8 + j;
        int col = nt * 8 + c2;
        int hl = j >> 1;
        float d0 = acc[j][0], d1 = acc[j][1], d2 = acc[j][2], d3 = acc[j][3];
        float t0 = satt[col], t1 = satt[col + 1];
        float u0 = satd[col], u1 = satd[col + 1];
        psA[hl] += d0 * t0 + d1 * t1; pdA[hl] += d0 * u0 + d1 * u1;
        psB[hl] += d2 * t0 + d3 * t1; pdB[hl] += d2 * u0 + d3 * u1;
        if (rowA < NN) {
            __half2 p = __floats2half2_rn(d0, d1);
            *(uint32_t*)&g_h1[rowA * 128 + col] = *(uint32_t*)&p;
        }
        if (rowB < NN) {
            __half2 p = __floats2half2_rn(d2, d3);
            *(uint32_t*)&g_h1[rowB * 128 + col] = *(uint32_t*)&p;
        }
    }
#pragma unroll
    for (int h = 0; h < 4; h++) {
        psA[h] += __shfl_xor_sync(0xffffffffu, psA[h], 1);
        psA[h] += __shfl_xor_sync(0xffffffffu, psA[h], 2);
        pdA[h] += __shfl_xor_sync(0xffffffffu, pdA[h], 1);
        pdA[h] += __shfl_xor_sync(0xffffffffu, pdA[h], 2);
        psB[h] += __shfl_xor_sync(0xffffffffu, psB[h], 1);
        psB[h] += __shfl_xor_sync(0xffffffffu, psB[h], 2);
        pdB[h] += __shfl_xor_sync(0xffffffffu, pdB[h], 1);
        pdB[h] += __shfl_xor_sync(0xffffffffu, pdB[h], 2);
    }
    int c = lane & 3;
    int h = half * 4 + c;
    if (rowA < NN) { g_as1[rowA * 8 + h] = psA[c]; g_ad1[rowA * 8 + h] = pdA[c]; }
    if (rowB < NN) { g_as1[rowB * 8 + h] = psB[c]; g_ad1[rowB * 8 + h] = pdB[c]; }
}

// ==================== fused layer1: single-pass, MLP-4 gather (fp16 h1, fp16 o1 out) ====================
__global__ void l1_gather(const float* __restrict__ b1, int wbase, int wcount) {
    __shared__ float sex[8][8][33];
    int w = wbase + ((blockIdx.x * blockDim.x + threadIdx.x) >> 5);
    int wid = (threadIdx.x >> 5) & 7;
    int lane = threadIdx.x & 31;
    if (w >= wbase + wcount || w >= NN) return;
    int beg = g_rp[w], end = g_rp[w + 1];

    float4 ad0 = *(const float4*)&g_ad1[w * 8];
    float4 ad1v = *(const float4*)&g_ad1[w * 8 + 4];

    int h = lane >> 2;
    float dn[8] = {};
    float4 acc = make_float4(0.f, 0.f, 0.f, 0.f);

    for (int base = beg; base < end; base += 32) {
        int idx = base + lane;
        int sc = (idx < end) ? g_col[idx] : 0;
        float msk = (idx < end) ? 1.f : 0.f;
        {
            float4 s0 = *(const float4*)&g_as1[sc * 8];
            float4 s1 = *(const float4*)&g_as1[sc * 8 + 4];
            float e0 = __expf(lrelu(s0.x + ad0.x)) * msk;
            float e1 = __expf(lrelu(s0.y + ad0.y)) * msk;
            float e2 = __expf(lrelu(s0.z + ad0.z)) * msk;
            float e3 = __expf(lrelu(s0.w + ad0.w)) * msk;
            float e4 = __expf(lrelu(s1.x + ad1v.x)) * msk;
            float e5 = __expf(lrelu(s1.y + ad1v.y)) * msk;
            float e6 = __expf(lrelu(s1.z + ad1v.z)) * msk;
            float e7 = __expf(lrelu(s1.w + ad1v.w)) * msk;
            sex[wid][0][lane] = e0; dn[0] += e0;
            sex[wid][1][lane] = e1; dn[1] += e1;
            sex[wid][2][lane] = e2; dn[2] += e2;
            sex[wid][3][lane] = e3; dn[3] += e3;
            sex[wid][4][lane] = e4; dn[4] += e4;
            sex[wid][5][lane] = e5; dn[5] += e5;
            sex[wid][6][lane] = e6; dn[6] += e6;
            sex[wid][7][lane] = e7; dn[7] += e7;
        }
        __syncwarp();
        int n = min(32, end - base);
        int j = 0;
        for (; j + 4 <= n; j += 4) {
            int s0 = __shfl_sync(0xffffffffu, sc, j);
            int s1 = __shfl_sync(0xffffffffu, sc, j + 1);
            int s2 = __shfl_sync(0xffffffffu, sc, j + 2);
            int s3 = __shfl_sync(0xffffffffu, sc, j + 3);
            float a0 = sex[wid][h][j];
            float a1 = sex[wid][h][j + 1];
            float a2 = sex[wid][h][j + 2];
            float a3 = sex[wid][h][j + 3];
            uint2 r0 = *(const uint2*)&g_h1[s0 * 128 + lane * 4];
            uint2 r1 = *(const uint2*)&g_h1[s1 * 128 + lane * 4];
            uint2 r2 = *(const uint2*)&g_h1[s2 * 128 + lane * 4];
            uint2 r3 = *(const uint2*)&g_h1[s3 * 128 + lane * 4];
            float2 f0a = __half22float2(*(__half2*)&r0.x), f0b = __half22float2(*(__half2*)&r0.y);
            float2 f1a = __half22float2(*(__half2*)&r1.x), f1b = __half22float2(*(__half2*)&r1.y);
            float2 f2a = __half22float2(*(__half2*)&r2.x), f2b = __half22float2(*(__half2*)&r2.y);
            float2 f3a = __half22float2(*(__half2*)&r3.x), f3b = __half22float2(*(__half2*)&r3.y);
            acc.x += a0 * f0a.x; acc.y += a0 * f0a.y;
            acc.z += a0 * f0b.x; acc.w += a0 * f0b.y;
            acc.x += a1 * f1a.x; acc.y += a1 * f1a.y;
            acc.z += a1 * f1b.x; acc.w += a1 * f1b.y;
            acc.x += a2 * f2a.x; acc.y += a2 * f2a.y;
            acc.z += a2 * f2b.x; acc.w += a2 * f2b.y;
            acc.x += a3 * f3a.x; acc.y += a3 * f3a.y;
            acc.z += a3 * f3b.x; acc.w += a3 * f3b.y;
        }
        for (; j < n; j++) {
            int s0 = __shfl_sync(0xffffffffu, sc, j);
            float a0 = sex[wid][h][j];
            uint2 r0 = *(const uint2*)&g_h1[s0 * 128 + lane * 4];
            float2 f0a = __half22float2(*(__half2*)&r0.x), f0b = __half22float2(*(__half2*)&r0.y);
            acc.x += a0 * f0a.x; acc.y += a0 * f0a.y;
            acc.z += a0 * f0b.x; acc.w += a0 * f0b.y;
        }
        __syncwarp();
    }

#pragma unroll
    for (int hh = 0; hh < 8; hh++)
        for (int off = 16; off; off >>= 1)
            dn[hh] += __shfl_xor_sync(0xffffffffu, dn[hh], off);
    float rdn = 1.f / (dn[h] + 1e-16f);

    float4 bb = *(const float4*)&b1[lane * 4];
    acc.x = acc.x * rdn + bb.x;
    acc.y = acc.y * rdn + bb.y;
    acc.z = acc.z * rdn + bb.z;
    acc.w = acc.w * rdn + bb.w;
    acc.x = acc.x > 0.f ? acc.x : expm1f(acc.x);
    acc.y = acc.y > 0.f ? acc.y : expm1f(acc.y);
    acc.z = acc.z > 0.f ? acc.z : expm1f(acc.z);
    acc.w = acc.w > 0.f ? acc.w : expm1f(acc.w);
    __half2 p0 = __floats2half2_rn(acc.x, acc.y);
    __half2 p1 = __floats2half2_rn(acc.z, acc.w);
    uint2 pk;
    pk.x = *(uint32_t*)&p0;
    pk.y = *(uint32_t*)&p1;
    *(uint2*)&g_o1h[w * 128 + lane * 4] = pk;
}

// ==================== GEMM2 (128->40, LDS.128 f32x2, fp16 input) with fused a2 dots ====================
__global__ void gemm2_kernel(const float* __restrict__ W,
                             const float* __restrict__ atts, const float* __restrict__ attd,
                             int rbase) {
    extern __shared__ float sm[];
    float* xs = sm + 5120;
    float* sa = sm + 5120 + 8448;
    float* sd = sa + 64;
    int t = threadIdx.x;
    int ct = t % 10, rt = t / 10;
    int row0 = rbase + blockIdx.x * 64;

    for (int i = t; i < 5120; i += 160) {
        int k = i / 40, c = i % 40;
        sm[(k >> 2) * 160 + (c & 3) * 40 + (c >> 2) * 4 + (k & 3)] = W[i];
    }
    for (int i = t; i < 2048; i += 160) {
        int r = i >> 5, k4 = (i & 31) * 4;
        int row = row0 + r;
        float4 v;
        if (row < NN) {
            uint2 pk = *(const uint2*)&g_o1h[row * 128 + k4];
            float2 a = __half22float2(*(__half2*)&pk.x);
            float2 b = __half22float2(*(__half2*)&pk.y);
            v = make_float4(a.x, a.y, b.x, b.y);
        } else {
            v = make_float4(0.f, 0.f, 0.f, 0.f);
        }
        *(float4*)&xs[r * 132 + k4] = v;
    }
    if (t < 64) { sa[t] = 0.f; sd[t] = 0.f; }
    __syncthreads();

    u64 acc2[4][4];
#pragma unroll
    for (int i = 0; i < 4; i++)
#pragma unroll
        for (int c = 0; c < 4; c++) acc2[i][c] = 0ull;

#pragma unroll 2
    for (int kpp = 0; kpp < 32; kpp++) {
        const float* wb = sm + kpp * 160 + 4 * ct;
        ulonglong2 w0 = *(const ulonglong2*)(wb);
        ulonglong2 w1 = *(const ulonglong2*)(wb + 40);
        ulonglong2 w2 = *(const ulonglong2*)(wb + 80);
        ulonglong2 w3 = *(const ulonglong2*)(wb + 120);
#pragma unroll
        for (int i = 0; i < 4; i++) {
            ulonglong2 xp = *(const ulonglong2*)&xs[(rt * 4 + i) * 132 + 4 * kpp];
            ffma2(acc2[i][0], xp.x, w0.x); ffma2(acc2[i][0], xp.y, w0.y);
            ffma2(acc2[i][1], xp.x, w1.x); ffma2(acc2[i][1], xp.y, w1.y);
            ffma2(acc2[i][2], xp.x, w2.x); ffma2(acc2[i][2], xp.y, w2.y);
            ffma2(acc2[i][3], xp.x, w3.x); ffma2(acc2[i][3], xp.y, w3.y);
        }
    }

    float4 avs = *(const float4*)&atts[4 * ct];
    float4 avd = *(const float4*)&attd[4 * ct];
#pragma unroll
    for (int i = 0; i < 4; i++) {
        float a[4];
#pragma unroll
        for (int c = 0; c < 4; c++) {
            float lo, hi; upk2(lo, hi, acc2[i][c]);
            a[c] = lo + hi;
        }
        int row = row0 + rt * 4 + i;
        if (row < NN)
            *(float4*)&g_z[row * 40 + 4 * ct] = make_float4(a[0], a[1], a[2], a[3]);
        float ps = a[0] * avs.x + a[1] * avs.y + a[2] * avs.z + a[3] * avs.w;
        float pd = a[0] * avd.x + a[1] * avd.y + a[2] * avd.z + a[3] * avd.w;
        atomicAdd(&sa[rt * 4 + i], ps);
        atomicAdd(&sd[rt * 4 + i], pd);
    }
    __syncthreads();
    if (t < 64) {
        int row = row0 + t;
        if (row < NN) { g_as2[row] = sa[t]; g_ad2[row] = sd[t]; }
    }
}

// ==================== fused layer2: single-pass, MLP-4 + bias + log_softmax ====================
__global__ void l2_gather(float* __restrict__ out, const float* __restrict__ b2) {
    int w = (blockIdx.x * blockDim.x + threadIdx.x) >> 5;
    int lane = threadIdx.x & 31;
    if (w >= NN) return;
    int beg = g_rp[w], end = g_rp[w + 1];
    float adw = g_ad2[w];

    float dn = 0.f;
    float a1 = 0.f, a2 = 0.f;
    for (int base = beg; base < end; base += 32) {
        int idx = base + lane;
        int sc = (idx < end) ? g_col[idx] : 0;
        float ex = (idx < end) ? __expf(lrelu(g_as2[sc] + adw)) : 0.f;
        dn += ex;
        int n = min(32, end - base);
        int j = 0;
        for (; j + 4 <= n; j += 4) {
            float al0 = __shfl_sync(0xffffffffu, ex, j);
            float al1 = __shfl_sync(0xffffffffu, ex, j + 1);
            float al2 = __shfl_sync(0xffffffffu, ex, j + 2);
            float al3 = __shfl_sync(0xffffffffu, ex, j + 3);
            int s0 = __shfl_sync(0xffffffffu, sc, j);
            int s1 = __shfl_sync(0xffffffffu, sc, j + 1);
            int s2 = __shfl_sync(0xffffffffu, sc, j + 2);
            int s3 = __shfl_sync(0xffffffffu, sc, j + 3);
            float z00 = g_z[s0 * 40 + lane];
            float z10 = g_z[s1 * 40 + lane];
            float z20 = g_z[s2 * 40 + lane];
            float z30 = g_z[s3 * 40 + lane];
            float z01 = (lane < 8) ? g_z[s0 * 40 + 32 + lane] : 0.f;
            float z11 = (lane < 8) ? g_z[s1 * 40 + 32 + lane] : 0.f;
            float z21 = (lane < 8) ? g_z[s2 * 40 + 32 + lane] : 0.f;
            float z31 = (lane < 8) ? g_z[s3 * 40 + 32 + lane] : 0.f;
            a1 += al0 * z00 + al1 * z10 + al2 * z20 + al3 * z30;
            a2 += al0 * z01 + al1 * z11 + al2 * z21 + al3 * z31;
        }
        for (; j < n; j++) {
            float al0 = __shfl_sync(0xffffffffu, ex, j);
            int s0 = __shfl_sync(0xffffffffu, sc, j);
            a1 += al0 * g_z[s0 * 40 + lane];
            if (lane < 8) a2 += al0 * g_z[s0 * 40 + 32 + lane];
        }
    }
    for (int off = 16; off; off >>= 1)
        dn += __shfl_xor_sync(0xffffffffu, dn, off);
    float rdn = 1.f / (dn + 1e-16f);

    float v1 = a1 * rdn + b2[lane];
    float v2 = (lane < 8) ? a2 * rdn + b2[32 + lane] : -1e30f;
    float m = fmaxf(v1, v2);
    for (int o = 16; o; o >>= 1) m = fmaxf(m, __shfl_xor_sync(0xffffffffu, m, o));
    float s = expf(v1 - m) + ((lane < 8) ? expf(v2 - m) : 0.f);
    for (int o = 16; o; o >>= 1) s += __shfl_xor_sync(0xffffffffu, s, o);
    float ls = m + logf(s);
    out[w * 40 + lane] = v1 - ls;
    if (lane < 8) out[w * 40 + 32 + lane] = v2 - ls;
}

// ==================== launch ====================
extern "C" void kernel_launch(void* const* d_in, const int* in_sizes, int n_in,
                              void* d_out, int out_size) {
    const float* x   = (const float*)d_in[0];
    const int*   ei  = (const int*)d_in[1];
    const float* W1  = (const float*)d_in[2];
    const float* as1 = (const float*)d_in[3];
    const float* ad1 = (const float*)d_in[4];
    const float* b1  = (const float*)d_in[5];
    const float* W2  = (const float*)d_in[6];
    const float* as2 = (const float*)d_in[7];
    const float* ad2 = (const float*)d_in[8];
    const float* b2  = (const float*)d_in[9];
    float* out = (float*)d_out;

    static cudaStream_t sB = nullptr;
    static cudaEvent_t evF = nullptr, evJ = nullptr, evA = nullptr, evB = nullptr;
    if (!sB) {
        cudaStreamCreateWithFlags(&sB, cudaStreamNonBlocking);
        cudaEventCreateWithFlags(&evF, cudaEventDisableTiming);
        cudaEventCreateWithFlags(&evJ, cudaEventDisableTiming);
        cudaEventCreateWithFlags(&evA, cudaEventDisableTiming);
        cudaEventCreateWithFlags(&evB, cudaEventDisableTiming);
    }

    const int SM2 = (5120 + 64 * 132 + 128) * 4;
    cudaFuncSetAttribute(gemm1_tc, cudaFuncAttributeMaxDynamicSharedMemorySize, G1_SMEM);
    cudaFuncSetAttribute(gemm2_kernel, cudaFuncAttributeMaxDynamicSharedMemorySize, SM2);

    // fork: CSR build on side stream; W-prep + tensor-core gemm1 on main stream.
    cudaEventRecord(evF, 0);
    cudaStreamWaitEvent(sB, evF, 0);

    w_prep<<<16, 256>>>(W1);                                  // main
    hist_kernel<<<(ET + 255) / 256, 256, 0, sB>>>(ei);
    scan1<<<NB, 1024, 0, sB>>>();
    gemm1_tc<<<(NN + 63) / 64, 256, G1_SMEM>>>(x, as1, ad1);  // main, profiled slot 3
    scan2<<<1, 128, 0, sB>>>();
    scan3<<<(NN + 255) / 256, 256, 0, sB>>>();
    scatter<<<(ET + 255) / 256, 256, 0, sB>>>(ei);
    cudaEventRecord(evJ, sB);

    cudaStreamWaitEvent(0, evJ, 0);

    // pipelined tail: l1a -> (gemm2a on side || l1b on main) -> gemm2b -> l2
    l1_gather<<<(N1 / 8), 256>>>(b1, 0, N1);                  // nodes [0, N1)
    cudaEventRecord(evA, 0);
    l1_gather<<<((NN - N1 + 7) / 8), 256>>>(b1, N1, NN - N1); // nodes [N1, NN)

    cudaStreamWaitEvent(sB, evA, 0);
    gemm2_kernel<<<N1 / 64, 160, SM2, sB>>>(W2, as2, ad2, 0);
    cudaEventRecord(evB, sB);

    gemm2_kernel<<<(NN - N1 + 63) / 64, 160, SM2>>>(W2, as2, ad2, N1);

    cudaStreamWaitEvent(0, evB, 0);
    l2_gather<<<(NN * 32 + 255) / 256, 256>>>(out, b2);
}